// round 5
// baseline (speedup 1.0000x reference)
#include <cuda_runtime.h>
#include <math.h>

// ---------------- problem constants ----------------
#define BB 2
#define CC 32
#define COC 32
#define HID 16
#define K144 144
#define M4096 4096

typedef unsigned long long ull;

// ---------------- packed f32x2 helpers ----------------
__device__ __forceinline__ ull pk(float lo, float hi) {
    ull r; asm("mov.b64 %0, {%1,%2};" : "=l"(r) : "f"(lo), "f"(hi)); return r;
}
__device__ __forceinline__ ull splat(float v) { return pk(v, v); }
__device__ __forceinline__ float2 upk(ull v) {
    float2 r; asm("mov.b64 {%0,%1}, %2;" : "=f"(r.x), "=f"(r.y) : "l"(v)); return r;
}
__device__ __forceinline__ ull ffma2(ull a, ull b, ull c) {
    ull d; asm("fma.rn.f32x2 %0, %1, %2, %3;" : "=l"(d) : "l"(a), "l"(b), "l"(c)); return d;
}

// ---------------- device scratch ----------------
__device__ float2 g_S2[BB*CC*64*256];     // after y-DFT  [bc][x][ky*16+kz]
__device__ float2 g_XS[BB*CC*M4096];      // spectral modes [bc][m]
__device__ float2 g_C1P[BB*CC*4*K144];    // partial coeffs [bc][p][k]
__device__ float2 g_C3[BB*HID*K144];      // W1-applied coeffs [b][j][s*9+l]
__device__ float2 g_T2[BB*64*64*256];     // [b][x][y][j*16+kz]
__device__ int    g_shell[M4096];
__device__ float  g_YW[M4096*9];
__device__ float  g_YWs[M4096*9];
__device__ int    g_sorted[M4096];
__device__ int    g_off[17];
__device__ float2 g_TW[64];               // e^{+2*pi*i*j/64}
__device__ float2 g_WC[HID*CC];           // W1 @ W_fno
__device__ float2 g_BC[HID];              // W1 @ b_fno + b1

// ---------------- K0: tables (pure float32, matches numpy float32 chain) ----------------
__global__ void k0_init() {
    __shared__ int cnt[16];
    __shared__ float wS[16];
    __shared__ int off[17];
    int t = threadIdx.x;                      // 512
    if (t < 16) cnt[t] = 0;
    __syncthreads();
    float rmax  = __fsqrt_rn(192.0f);
    float denom = __fadd_rn(rmax, 1e-6f);
    for (int m = t; m < M4096; m += 512) {
        int ix = m >> 8, iy = (m >> 4) & 15, iz = m & 15;
        int fx = ix < 8 ? ix : ix - 16;
        int fy = iy < 8 ? iy : iy - 16;
        int fz = iz < 8 ? iz : iz - 16;
        int k2 = fx*fx + fy*fy + fz*fz;
        float r = __fsqrt_rn((float)k2);
        float q = __fmul_rn(__fdiv_rn(r, denom), 16.0f);
        int s = (int)q;
        if (s > 15) s = 15;
        g_shell[m] = s;
        atomicAdd(&cnt[s], 1);
        float inv = (k2 > 0) ? __fdiv_rn(1.0f, r) : 0.0f;
        float ux = fx * inv, uy = fy * inv, uz = fz * inv;
        float nzm = k2 > 0 ? 1.0f : 0.0f;
        float* Y = &g_YW[m * 9];
        Y[0] = 0.282095f;
        Y[1] = 0.488603f * uy;
        Y[2] = 0.488603f * uz;
        Y[3] = 0.488603f * ux;
        Y[4] = 1.092548f * ux * uy;
        Y[5] = 1.092548f * uy * uz;
        Y[6] = 0.315392f * (3.0f * uz * uz - nzm);
        Y[7] = 1.092548f * ux * uz;
        Y[8] = 0.546274f * (ux * ux - uy * uy);
    }
    __syncthreads();
    if (t < 16) wS[t] = __fdiv_rn(1.0f, __fsqrt_rn(fmaxf((float)cnt[t], 1.0f)));
    if (t == 0) {
        int acc = 0;
        for (int s = 0; s < 16; s++) { off[s] = acc; g_off[s] = acc; acc += cnt[s]; }
        off[16] = acc; g_off[16] = acc;
    }
    __syncthreads();
    for (int m = t; m < M4096; m += 512) {
        float w = wS[g_shell[m]];
        #pragma unroll
        for (int l = 0; l < 9; l++) g_YW[m*9+l] *= w;
    }
    __syncthreads();
    {
        int w = t >> 5, lane = t & 31;
        int s = w;
        int pos = off[s];
        for (int chunk = 0; chunk < 128; chunk++) {
            int m = chunk * 32 + lane;
            bool mine = (g_shell[m] == s);
            unsigned msk = __ballot_sync(0xffffffffu, mine);
            if (mine) {
                int p = pos + __popc(msk & ((1u << lane) - 1u));
                g_sorted[p] = m;
                #pragma unroll
                for (int l = 0; l < 9; l++) g_YWs[p*9+l] = g_YW[m*9+l];
            }
            pos += __popc(msk);
        }
    }
    if (t < 64) {
        float ang = (float)(2.0 * M_PI * (double)t / 64.0);
        g_TW[t] = make_float2(cosf(ang), sinf(ang));
    }
}

// ---------------- Kpre: fold W1 into the FNO skip ----------------
__global__ void kpre(const float* __restrict__ wfr, const float* __restrict__ wfi,
                     const float* __restrict__ bfr, const float* __restrict__ bfi,
                     const float* __restrict__ w1r, const float* __restrict__ w1i,
                     const float* __restrict__ b1r, const float* __restrict__ b1i) {
    int t = threadIdx.x;                 // 512
    int j = t >> 5, c = t & 31;
    float ar = 0.f, ai = 0.f;
    for (int o = 0; o < 32; o++) {
        float ax = w1r[j*32+o], ay = w1i[j*32+o];
        float bx = wfr[o*32+c], by = wfi[o*32+c];
        ar += ax*bx - ay*by;
        ai += ax*by + ay*bx;
    }
    g_WC[j*32+c] = make_float2(ar, ai);
    if (c == 0) {
        float br = b1r[j], bi = b1i[j];
        for (int o = 0; o < 32; o++) {
            float ax = w1r[j*32+o], ay = w1i[j*32+o];
            float bx = bfr[o], by = bfi[o];
            br += ax*bx - ay*by;
            bi += ax*by + ay*bx;
        }
        g_BC[j] = make_float2(br, bi);
    }
}

// ---------------- K12: fused forward z-DFT (conj-sym) + y-DFT, packed ----------------
__global__ void k12_fwd(const float* __restrict__ x) {
    __shared__ float  xp[64*65];
    __shared__ float2 S1[1024];
    __shared__ ull    twA[1024];     // (c, -s)
    __shared__ ull    twB[1024];     // (s, c)
    int blk = blockIdx.x;            // bc*64 + x
    int t = threadIdx.x;             // 256
    const float* src = x + (size_t)blk * 4096;
    for (int i = t; i < 4096; i += 256) xp[(i >> 6)*65 + (i & 63)] = src[i];
    for (int i = t; i < 1024; i += 256) {
        int k = i >> 6, j = i & 63;
        int fk = k < 8 ? k : k - 16;
        float2 w = g_TW[(j * fk) & 63];
        twA[i] = pk(w.x, -w.y);
        twB[i] = pk(w.y, w.x);
    }
    __syncthreads();
    // phase A: real z-DFT with conjugate symmetry
    {
        int y = t >> 2, q = t & 3;
        ull a0 = 0, a1 = 0, a2 = 0;
        const float* row = &xp[y*65];
        for (int z = 0; z < 64; z++) {
            ull sx = splat(row[z]);
            a0 = ffma2(sx, twA[q*64 + z], a0);
            a1 = ffma2(sx, twA[(q+4)*64 + z], a1);
            if (q == 0) a2 = ffma2(sx, twA[8*64 + z], a2);
        }
        float2 v0 = upk(a0), v1 = upk(a1), v2 = upk(a2);
        S1[y*16 + q]      = v0;
        S1[y*16 + q + 4]  = v1;
        S1[y*16 + 12 - q] = make_float2(v1.x, -v1.y);
        if (q > 0) S1[y*16 + 16 - q] = make_float2(v0.x, -v0.y);
        else       S1[y*16 + 8]      = v2;
    }
    __syncthreads();
    // phase B: complex y-DFT, packed
    {
        int ky = t >> 4, kz = t & 15;
        ull acc = 0;
        for (int y = 0; y < 64; y++) {
            float2 v = S1[y*16 + kz];
            acc = ffma2(splat(v.x), twA[ky*64 + y], acc);
            acc = ffma2(splat(v.y), twB[ky*64 + y], acc);
        }
        g_S2[(size_t)blk * 256 + t] = upk(acc);
    }
}

// ---------------- K3: forward x-DFT, packed ----------------
__global__ void k3_xdft() {
    __shared__ ull twA[1024];        // (c, -s), [kx*64+xx]
    __shared__ ull twB[1024];        // (s, c)
    int bc = blockIdx.x >> 2;
    int tq = blockIdx.x & 3;
    int tid = threadIdx.x;           // 256
    int kxg = tid >> 6, tl = tid & 63;
    int t = tq * 64 + tl;
    for (int i = tid; i < 1024; i += 256) {
        int k = i >> 6, j = i & 63;
        int fk = k < 8 ? k : k - 16;
        float2 w = g_TW[(j * fk) & 63];
        twA[i] = pk(w.x, -w.y);
        twB[i] = pk(w.y, w.x);
    }
    __syncthreads();
    ull acc[4] = {0, 0, 0, 0};
    const float2* src = g_S2 + (size_t)bc * 16384;
    for (int xx = 0; xx < 64; xx++) {
        float2 v = src[xx*256 + t];
        ull sx = splat(v.x), sy = splat(v.y);
        #pragma unroll
        for (int i = 0; i < 4; i++) {
            acc[i] = ffma2(sx, twA[(kxg*4 + i)*64 + xx], acc[i]);
            acc[i] = ffma2(sy, twB[(kxg*4 + i)*64 + xx], acc[i]);
        }
    }
    float2* dst = g_XS + (size_t)bc * 4096;
    #pragma unroll
    for (int i = 0; i < 4; i++) dst[(kxg*4 + i)*256 + t] = upk(acc[i]);
}

// ---------------- K4: basis projection (4-way split across blocks) ----------------
__global__ void k4_proj() {
    __shared__ float2 sxs[4096];
    int bc = blockIdx.x >> 2;
    int p  = blockIdx.x & 3;
    int tid = threadIdx.x;           // 256
    for (int i = tid; i < 4096; i += 256) sxs[i] = g_XS[(size_t)bc * 4096 + i];
    __syncthreads();
    if (tid < K144) {
        int k = tid;
        int s = k / 9, l = k - s * 9;
        int beg = g_off[s], end = g_off[s+1], len = end - beg;
        int i0 = beg + (len * p) / 4;
        int i1 = beg + (len * (p + 1)) / 4;
        ull acc = 0;
        for (int i = i0; i < i1; i++) {
            int m = g_sorted[i];
            float w = g_YWs[i*9 + l];
            float2 v = sxs[m];
            acc = ffma2(splat(w), pk(v.x, v.y), acc);
        }
        g_C1P[((size_t)bc*4 + p)*K144 + k] = upk(acc);
    }
}

// ---------------- K5: spectral conv fused with W1 ----------------
__global__ void k5_conv(const float* __restrict__ wr, const float* __restrict__ wi,
                        const float* __restrict__ w1r, const float* __restrict__ w1i) {
    __shared__ float2 cin[32];
    __shared__ float2 c2s[32];
    int blk = blockIdx.x;            // b*144 + sl
    int b = blk / K144, sl = blk - b * K144;
    int o = threadIdx.x;             // 32
    {
        size_t base = ((size_t)(b*32 + o))*4*K144 + sl;
        float2 a = g_C1P[base], bb = g_C1P[base + K144];
        float2 c = g_C1P[base + 2*K144], d = g_C1P[base + 3*K144];
        cin[o] = make_float2(a.x+bb.x+c.x+d.x, a.y+bb.y+c.y+d.y);
    }
    __syncwarp();
    const float* wrp = wr + (size_t)sl * 1024 + o;
    const float* wip = wi + (size_t)sl * 1024 + o;
    float ar = 0.f, ai = 0.f;
    #pragma unroll
    for (int i = 0; i < 32; i++) {
        float2 c = cin[i];
        float a = wrp[i*32], bb = wip[i*32];
        ar += c.x*a - c.y*bb;
        ai += c.x*bb + c.y*a;
    }
    const float invn = 1.0f / 262144.0f;
    c2s[o] = make_float2(ar*invn, ai*invn);
    __syncwarp();
    if (o < HID) {
        int j = o;
        float br = 0.f, bi = 0.f;
        #pragma unroll
        for (int q = 0; q < 32; q++) {
            float ax = w1r[j*32+q], ay = w1i[j*32+q];
            float2 c = c2s[q];
            br += ax*c.x - ay*c.y;
            bi += ax*c.y + ay*c.x;
        }
        g_C3[((size_t)(b*HID + j))*K144 + sl] = make_float2(br, bi);
    }
}

// ---------------- K67: inverse basis + inverse x-DFT + inverse y-DFT (packed) ----------------
__global__ void k67_inv() {
    __shared__ ull c3[K144];
    __shared__ ull twiA[1024];       // (c, s)
    __shared__ ull twiB[1024];       // (-s, c)
    __shared__ float2 S[256];
    int bj = blockIdx.x >> 4;        // b*16 + j
    int xch = blockIdx.x & 15;
    int b = bj >> 4, j = bj & 15;
    int t = threadIdx.x;             // 256
    if (t < K144) {
        float2 v = g_C3[(size_t)bj*K144 + t];
        c3[t] = pk(v.x, v.y);
    }
    for (int i = t; i < 1024; i += 256) {
        int k = i >> 6, jj = i & 63;
        int fk = k < 8 ? k : k - 16;
        float2 w = g_TW[(jj * fk) & 63];
        twiA[i] = pk(w.x, w.y);
        twiB[i] = pk(-w.y, w.x);
    }
    __syncthreads();
    // inverse basis: xs2[kx] for t = ky*16+kz
    ull xs2[16];
    #pragma unroll
    for (int kx = 0; kx < 16; kx++) {
        int m = (kx << 8) | t;
        int s = g_shell[m];
        const float* yw = &g_YW[m*9];
        ull acc = 0;
        #pragma unroll
        for (int l = 0; l < 9; l++) acc = ffma2(splat(yw[l]), c3[s*9 + l], acc);
        xs2[kx] = acc;
    }
    for (int xi = 0; xi < 4; xi++) {
        int xx = xch * 4 + xi;
        ull o = 0;
        #pragma unroll
        for (int kx = 0; kx < 16; kx++) {
            float2 v = upk(xs2[kx]);
            o = ffma2(splat(v.x), twiA[kx*64 + xx], o);
            o = ffma2(splat(v.y), twiB[kx*64 + xx], o);
        }
        S[t] = upk(o);
        __syncthreads();
        {
            int y = t & 63, kzg = t >> 6;
            ull acc[4] = {0, 0, 0, 0};
            for (int ky = 0; ky < 16; ky++) {
                ull wA = twiA[ky*64 + y], wB = twiB[ky*64 + y];
                #pragma unroll
                for (int i = 0; i < 4; i++) {
                    float2 v = S[ky*16 + kzg*4 + i];
                    acc[i] = ffma2(splat(v.x), wA, acc[i]);
                    acc[i] = ffma2(splat(v.y), wB, acc[i]);
                }
            }
            size_t base = (((size_t)b*64 + xx)*64 + y)*256 + j*16 + kzg*4;
            #pragma unroll
            for (int i = 0; i < 4; i++) g_T2[base + i] = upk(acc[i]);
        }
        __syncthreads();
    }
}

// ---------------- K8: fused epilogue, j/o-pair packed, h in registers ----------------
__device__ __forceinline__ float gelu_t(float v) {
    float u = 0.7978845608028654f * (v + 0.044715f * v * v * v);
    float e = __expf(2.0f * u);
    float th = 1.0f - 2.0f / (e + 1.0f);
    return 0.5f * v * (1.0f + th);
}

#define K8_SMEM 57728

__global__ void __launch_bounds__(256, 2)
k8_final(const float* __restrict__ x,
         const float* __restrict__ wgr,
         const float* __restrict__ w2r, const float* __restrict__ w2i,
         const float* __restrict__ b2r,
         float* __restrict__ out) {
    extern __shared__ char sm[];
    float* s_x   = (float*)sm;                  // [4][32][64] 32KB
    float* s_t2x = (float*)(sm + 32768);        // [4][16kz][16j] 4KB
    float* s_t2y = (float*)(sm + 36864);        // 4KB
    float* s_twc = (float*)(sm + 40960);        // [16kz][64z] 4KB
    float* s_tws = (float*)(sm + 45056);        // 4KB
    float* s_wcR = (float*)(sm + 49152);        // [32c][16j] 2KB
    float* s_wcI = (float*)(sm + 51200);        // 2KB
    float* s_w2r = (float*)(sm + 53248);        // [16j][32o] 2KB
    float* s_w2n = (float*)(sm + 55296);        // -w2i 2KB
    float* s_bcR = (float*)(sm + 57344);        // [16]
    float* s_bcI = (float*)(sm + 57408);        // [16]
    float* s_b2  = (float*)(sm + 57472);        // [32]
    float* s_wg  = (float*)(sm + 57600);        // [32]

    int blk = blockIdx.x;
    int b  = blk >> 10;
    int xc = (blk >> 4) & 63;
    int y0 = (blk & 15) * 4;
    int t = threadIdx.x;

    for (int i = t; i < 2048; i += 256) {
        int line = i >> 9, c = (i >> 4) & 31, zq = i & 15;
        float4 v = *(const float4*)&x[(((size_t)(b*32+c))*64 + xc)*4096 + (size_t)(y0+line)*64 + zq*4];
        *(float4*)&s_x[(line*32+c)*64 + zq*4] = v;
    }
    for (int i = t; i < 1024; i += 256) {
        int line = i >> 8, q = i & 255;
        int j = q >> 4, kz = q & 15;
        float2 v = g_T2[((((size_t)b*64 + xc)*64) + (y0+line))*256 + q];
        s_t2x[(line*16 + kz)*16 + j] = v.x;
        s_t2y[(line*16 + kz)*16 + j] = v.y;
    }
    for (int i = t; i < 1024; i += 256) {
        int kz = i >> 6, z = i & 63;
        int fk = kz < 8 ? kz : kz - 16;
        float2 w = g_TW[(z*fk) & 63];
        s_twc[i] = w.x;
        s_tws[i] = w.y;
    }
    for (int i = t; i < 512; i += 256) {
        int c = i >> 4, j = i & 15;
        float2 wv = g_WC[j*32 + c];
        s_wcR[c*16 + j] = wv.x;
        s_wcI[c*16 + j] = wv.y;
        int jj = i >> 5, o = i & 31;
        s_w2r[jj*32 + o] = w2r[o*16 + jj];
        s_w2n[jj*32 + o] = -w2i[o*16 + jj];
    }
    if (t < 32) {
        s_b2[t] = b2r[t];
        s_wg[t] = wgr[t];
        if (t < 16) { float2 v = g_BC[t]; s_bcR[t] = v.x; s_bcI[t] = v.y; }
    }
    __syncthreads();

    int line = t >> 6, z = t & 63;
    const float* xl = &s_x[line*2048];

    // ---- pass 1: g = ifft_z(t2) + Wc*x + bc (packed over j-pairs) ----
    ull accR[8], accI[8];
    #pragma unroll
    for (int jp = 0; jp < 8; jp++) {
        accR[jp] = *(const ull*)&s_bcR[jp*2];
        accI[jp] = *(const ull*)&s_bcI[jp*2];
    }
    #pragma unroll
    for (int kz = 0; kz < 16; kz++) {
        float cw = s_twc[kz*64 + z], sw = s_tws[kz*64 + z];
        ull sc = splat(cw), ss = splat(sw), sn = splat(-sw);
        const ulonglong2* tx = (const ulonglong2*)&s_t2x[(line*16 + kz)*16];
        const ulonglong2* ty = (const ulonglong2*)&s_t2y[(line*16 + kz)*16];
        #pragma unroll
        for (int p = 0; p < 4; p++) {
            ulonglong2 a = tx[p], bv = ty[p];
            accR[2*p]   = ffma2(a.x,  sc, accR[2*p]);
            accR[2*p]   = ffma2(bv.x, sn, accR[2*p]);
            accI[2*p]   = ffma2(a.x,  ss, accI[2*p]);
            accI[2*p]   = ffma2(bv.x, sc, accI[2*p]);
            accR[2*p+1] = ffma2(a.y,  sc, accR[2*p+1]);
            accR[2*p+1] = ffma2(bv.y, sn, accR[2*p+1]);
            accI[2*p+1] = ffma2(a.y,  ss, accI[2*p+1]);
            accI[2*p+1] = ffma2(bv.y, sc, accI[2*p+1]);
        }
    }
    #pragma unroll 4
    for (int c = 0; c < 32; c++) {
        ull sx = splat(xl[c*64 + z]);
        const ulonglong2* wr = (const ulonglong2*)&s_wcR[c*16];
        const ulonglong2* wi = (const ulonglong2*)&s_wcI[c*16];
        #pragma unroll
        for (int p = 0; p < 4; p++) {
            ulonglong2 a = wr[p], bv = wi[p];
            accR[2*p]   = ffma2(a.x,  sx, accR[2*p]);
            accR[2*p+1] = ffma2(a.y,  sx, accR[2*p+1]);
            accI[2*p]   = ffma2(bv.x, sx, accI[2*p]);
            accI[2*p+1] = ffma2(bv.y, sx, accI[2*p+1]);
        }
    }

    // ---- gelu (h stays in registers) ----
    float hrf[16], hif[16];
    #pragma unroll
    for (int jp = 0; jp < 8; jp++) {
        float2 r  = upk(accR[jp]);
        float2 im = upk(accI[jp]);
        hrf[2*jp]   = gelu_t(r.x);
        hrf[2*jp+1] = gelu_t(r.y);
        hif[2*jp]   = gelu_t(im.x);
        hif[2*jp+1] = gelu_t(im.y);
    }

    // ---- pass 2: out = Re(W2 h) + b2 + x*wg (packed over o-pairs) ----
    ull accO[16];
    #pragma unroll
    for (int op = 0; op < 16; op++) {
        ull b2p = *(const ull*)&s_b2[op*2];
        ull wgp = *(const ull*)&s_wg[op*2];
        ull xp  = pk(xl[(op*2)*64 + z], xl[(op*2+1)*64 + z]);
        accO[op] = ffma2(xp, wgp, b2p);
    }
    #pragma unroll
    for (int j = 0; j < 16; j++) {
        ull shr = splat(hrf[j]), shi = splat(hif[j]);
        const ulonglong2* wr = (const ulonglong2*)&s_w2r[j*32];
        const ulonglong2* wn = (const ulonglong2*)&s_w2n[j*32];
        #pragma unroll
        for (int p = 0; p < 8; p++) {
            ulonglong2 a = wr[p], bv = wn[p];
            accO[2*p]   = ffma2(a.x,  shr, accO[2*p]);
            accO[2*p]   = ffma2(bv.x, shi, accO[2*p]);
            accO[2*p+1] = ffma2(a.y,  shr, accO[2*p+1]);
            accO[2*p+1] = ffma2(bv.y, shi, accO[2*p+1]);
        }
    }
    int y = y0 + line;
    size_t obase = (((size_t)(b*32))*64 + xc)*4096 + (size_t)y*64 + z;
    #pragma unroll
    for (int op = 0; op < 16; op++) {
        float2 v = upk(accO[op]);
        out[obase + (size_t)(op*2)   * 262144] = v.x;
        out[obase + (size_t)(op*2+1) * 262144] = v.y;
    }
}

// ---------------- launch ----------------
extern "C" void kernel_launch(void* const* d_in, const int* in_sizes, int n_in,
                              void* d_out, int out_size) {
    const float* x    = (const float*)d_in[0];
    const float* wfr  = (const float*)d_in[1];
    const float* wfi  = (const float*)d_in[2];
    const float* bfr  = (const float*)d_in[3];
    const float* bfi  = (const float*)d_in[4];
    const float* wgr  = (const float*)d_in[5];
    const float* wsr  = (const float*)d_in[7];
    const float* wsi  = (const float*)d_in[8];
    const float* w1r  = (const float*)d_in[9];
    const float* w1i  = (const float*)d_in[10];
    const float* b1r  = (const float*)d_in[11];
    const float* b1i  = (const float*)d_in[12];
    const float* w2r  = (const float*)d_in[13];
    const float* w2i  = (const float*)d_in[14];
    const float* b2r  = (const float*)d_in[15];
    float* out = (float*)d_out;

    cudaFuncSetAttribute(k8_final, cudaFuncAttributeMaxDynamicSharedMemorySize, K8_SMEM);

    k0_init<<<1, 512>>>();
    kpre<<<1, 512>>>(wfr, wfi, bfr, bfi, w1r, w1i, b1r, b1i);
    k12_fwd<<<BB*CC*64, 256>>>(x);
    k3_xdft<<<BB*CC*4, 256>>>();
    k4_proj<<<BB*CC*4, 256>>>();
    k5_conv<<<BB*K144, 32>>>(wsr, wsi, w1r, w1i);
    k67_inv<<<BB*HID*16, 256>>>();
    k8_final<<<BB*64*16, 256, K8_SMEM>>>(x, wgr, w2r, w2i, b2r, out);
}

// round 6
// speedup vs baseline: 1.2729x; 1.2729x over previous
#include <cuda_runtime.h>
#include <math.h>

// ---------------- problem constants ----------------
#define BB 2
#define CC 32
#define HID 16
#define K144 144
#define M4096 4096

typedef unsigned long long ull;

// ---------------- packed f32x2 helpers ----------------
__device__ __forceinline__ ull pk(float lo, float hi) {
    ull r; asm("mov.b64 %0, {%1,%2};" : "=l"(r) : "f"(lo), "f"(hi)); return r;
}
__device__ __forceinline__ ull splat(float v) { return pk(v, v); }
__device__ __forceinline__ float2 upk(ull v) {
    float2 r; asm("mov.b64 {%0,%1}, %2;" : "=f"(r.x), "=f"(r.y) : "l"(v)); return r;
}
__device__ __forceinline__ ull ffma2(ull a, ull b, ull c) {
    ull d; asm("fma.rn.f32x2 %0, %1, %2, %3;" : "=l"(d) : "l"(a), "l"(b), "l"(c)); return d;
}

// ---------------- device scratch ----------------
__device__ __align__(16) float2 g_S2[BB*CC*64*256];
__device__ __align__(16) float2 g_XS[BB*CC*M4096];
__device__ __align__(16) float2 g_C1P[BB*CC*4*K144];
__device__ __align__(16) float2 g_C3[BB*HID*K144];
__device__ __align__(16) float2 g_T2[BB*64*64*256];
__device__ int    g_shell[M4096];
__device__ __align__(16) float g_YW[M4096*9];
__device__ __align__(16) float g_YWs[M4096*9];
__device__ int    g_sorted[M4096];
__device__ int    g_off[17];
__device__ float2 g_TW[64];
__device__ float2 g_WC[HID*CC];
__device__ float2 g_BC[HID];

// ---------------- K0: tables (pure float32) ----------------
__global__ void k0_init() {
    __shared__ int cnt[16];
    __shared__ float wS[16];
    __shared__ int off[17];
    int t = threadIdx.x;                      // 512
    if (t < 16) cnt[t] = 0;
    __syncthreads();
    float rmax  = __fsqrt_rn(192.0f);
    float denom = __fadd_rn(rmax, 1e-6f);
    for (int m = t; m < M4096; m += 512) {
        int ix = m >> 8, iy = (m >> 4) & 15, iz = m & 15;
        int fx = ix < 8 ? ix : ix - 16;
        int fy = iy < 8 ? iy : iy - 16;
        int fz = iz < 8 ? iz : iz - 16;
        int k2 = fx*fx + fy*fy + fz*fz;
        float r = __fsqrt_rn((float)k2);
        float q = __fmul_rn(__fdiv_rn(r, denom), 16.0f);
        int s = (int)q;
        if (s > 15) s = 15;
        g_shell[m] = s;
        atomicAdd(&cnt[s], 1);
        float inv = (k2 > 0) ? __fdiv_rn(1.0f, r) : 0.0f;
        float ux = fx * inv, uy = fy * inv, uz = fz * inv;
        float nzm = k2 > 0 ? 1.0f : 0.0f;
        float* Y = &g_YW[m * 9];
        Y[0] = 0.282095f;
        Y[1] = 0.488603f * uy;
        Y[2] = 0.488603f * uz;
        Y[3] = 0.488603f * ux;
        Y[4] = 1.092548f * ux * uy;
        Y[5] = 1.092548f * uy * uz;
        Y[6] = 0.315392f * (3.0f * uz * uz - nzm);
        Y[7] = 1.092548f * ux * uz;
        Y[8] = 0.546274f * (ux * ux - uy * uy);
    }
    __syncthreads();
    if (t < 16) wS[t] = __fdiv_rn(1.0f, __fsqrt_rn(fmaxf((float)cnt[t], 1.0f)));
    if (t == 0) {
        int acc = 0;
        for (int s = 0; s < 16; s++) { off[s] = acc; g_off[s] = acc; acc += cnt[s]; }
        off[16] = acc; g_off[16] = acc;
    }
    __syncthreads();
    for (int m = t; m < M4096; m += 512) {
        float w = wS[g_shell[m]];
        #pragma unroll
        for (int l = 0; l < 9; l++) g_YW[m*9+l] *= w;
    }
    __syncthreads();
    {
        int w = t >> 5, lane = t & 31;
        int s = w;
        int pos = off[s];
        for (int chunk = 0; chunk < 128; chunk++) {
            int m = chunk * 32 + lane;
            bool mine = (g_shell[m] == s);
            unsigned msk = __ballot_sync(0xffffffffu, mine);
            if (mine) {
                int p = pos + __popc(msk & ((1u << lane) - 1u));
                g_sorted[p] = m;
                #pragma unroll
                for (int l = 0; l < 9; l++) g_YWs[p*9+l] = g_YW[m*9+l];
            }
            pos += __popc(msk);
        }
    }
    if (t < 64) {
        float ang = (float)(2.0 * M_PI * (double)t / 64.0);
        g_TW[t] = make_float2(cosf(ang), sinf(ang));
    }
}

// ---------------- Kpre ----------------
__global__ void kpre(const float* __restrict__ wfr, const float* __restrict__ wfi,
                     const float* __restrict__ bfr, const float* __restrict__ bfi,
                     const float* __restrict__ w1r, const float* __restrict__ w1i,
                     const float* __restrict__ b1r, const float* __restrict__ b1i) {
    int t = threadIdx.x;                 // 512
    int j = t >> 5, c = t & 31;
    float ar = 0.f, ai = 0.f;
    for (int o = 0; o < 32; o++) {
        float ax = w1r[j*32+o], ay = w1i[j*32+o];
        float bx = wfr[o*32+c], by = wfi[o*32+c];
        ar += ax*bx - ay*by;
        ai += ax*by + ay*bx;
    }
    g_WC[j*32+c] = make_float2(ar, ai);
    if (c == 0) {
        float br = b1r[j], bi = b1i[j];
        for (int o = 0; o < 32; o++) {
            float ax = w1r[j*32+o], ay = w1i[j*32+o];
            float bx = bfr[o], by = bfi[o];
            br += ax*bx - ay*by;
            bi += ax*by + ay*bx;
        }
        g_BC[j] = make_float2(br, bi);
    }
}

// ---------------- K12: forward z-DFT (conj-sym) + y-DFT, vectorized ----------------
__global__ void k12_fwd(const float* __restrict__ x) {
    __shared__ __align__(16) float xp[64*68];    // padded rows (float4-aligned)
    __shared__ float2 S1[1024];
    __shared__ __align__(16) ull twA[16*66];     // (c,-s), padded stride 66
    __shared__ __align__(16) ull twB[16*66];     // (s, c)
    int blk = blockIdx.x;            // bc*64 + x
    int t = threadIdx.x;             // 256
    const float* src = x + (size_t)blk * 4096;
    for (int i = t; i < 1024; i += 256) {
        float4 v = *(const float4*)&src[i*4];
        int y = i >> 4, z0 = (i & 15) * 4;
        *(float4*)&xp[y*68 + z0] = v;
    }
    for (int i = t; i < 1024; i += 256) {
        int k = i >> 6, j = i & 63;
        int fk = k < 8 ? k : k - 16;
        float2 w = g_TW[(j * fk) & 63];
        twA[k*66 + j] = pk(w.x, -w.y);
        twB[k*66 + j] = pk(w.y, w.x);
    }
    __syncthreads();
    // phase A: real z-DFT (compute kz = q, q+4, and 8 if q==0), vectorized
    {
        int y = t >> 2, q = t & 3;
        ull a0 = 0, a1 = 0, a2 = 0;
        const float4* row4 = (const float4*)&xp[y*68];
        const ulonglong2* tA0 = (const ulonglong2*)&twA[q*66];
        const ulonglong2* tA1 = (const ulonglong2*)&twA[(q+4)*66];
        const ulonglong2* tA2 = (const ulonglong2*)&twA[8*66];
        #pragma unroll
        for (int zi = 0; zi < 16; zi++) {
            float4 r = row4[zi];
            ull r0 = splat(r.x), r1 = splat(r.y), r2 = splat(r.z), r3 = splat(r.w);
            ulonglong2 wa = tA0[2*zi], wb = tA0[2*zi+1];
            a0 = ffma2(r0, wa.x, a0); a0 = ffma2(r1, wa.y, a0);
            a0 = ffma2(r2, wb.x, a0); a0 = ffma2(r3, wb.y, a0);
            ulonglong2 wc = tA1[2*zi], wd = tA1[2*zi+1];
            a1 = ffma2(r0, wc.x, a1); a1 = ffma2(r1, wc.y, a1);
            a1 = ffma2(r2, wd.x, a1); a1 = ffma2(r3, wd.y, a1);
            if (q == 0) {
                ulonglong2 we = tA2[2*zi], wf = tA2[2*zi+1];
                a2 = ffma2(r0, we.x, a2); a2 = ffma2(r1, we.y, a2);
                a2 = ffma2(r2, wf.x, a2); a2 = ffma2(r3, wf.y, a2);
            }
        }
        float2 v0 = upk(a0), v1 = upk(a1), v2 = upk(a2);
        S1[y*16 + q]      = v0;
        S1[y*16 + q + 4]  = v1;
        S1[y*16 + 12 - q] = make_float2(v1.x, -v1.y);
        if (q > 0) S1[y*16 + 16 - q] = make_float2(v0.x, -v0.y);
        else       S1[y*16 + 8]      = v2;
    }
    __syncthreads();
    // phase B: complex y-DFT, 2 chains
    {
        int ky = t >> 4, kz = t & 15;
        ull acc0 = 0, acc1 = 0;
        #pragma unroll 4
        for (int y2 = 0; y2 < 64; y2 += 2) {
            float2 u0 = S1[y2*16 + kz];
            float2 u1 = S1[(y2+1)*16 + kz];
            ulonglong2 wA = *(const ulonglong2*)&twA[ky*66 + y2];
            ulonglong2 wB = *(const ulonglong2*)&twB[ky*66 + y2];
            acc0 = ffma2(splat(u0.x), wA.x, acc0);
            acc0 = ffma2(splat(u0.y), wB.x, acc0);
            acc1 = ffma2(splat(u1.x), wA.y, acc1);
            acc1 = ffma2(splat(u1.y), wB.y, acc1);
        }
        float2 r0 = upk(acc0), r1 = upk(acc1);
        g_S2[(size_t)blk * 256 + t] = make_float2(r0.x + r1.x, r0.y + r1.y);
    }
}

// ---------------- K3: forward x-DFT, MLP-4 ----------------
__global__ void k3_xdft() {
    __shared__ ull twA[1024];        // (c, -s), [kx*64+xx] (warp-uniform access)
    __shared__ ull twB[1024];        // (s, c)
    int bc = blockIdx.x >> 2;
    int tq = blockIdx.x & 3;
    int tid = threadIdx.x;           // 256
    int kxg = tid >> 6, tl = tid & 63;
    int t = tq * 64 + tl;
    for (int i = tid; i < 1024; i += 256) {
        int k = i >> 6, j = i & 63;
        int fk = k < 8 ? k : k - 16;
        float2 w = g_TW[(j * fk) & 63];
        twA[i] = pk(w.x, -w.y);
        twB[i] = pk(w.y, w.x);
    }
    __syncthreads();
    ull acc[4] = {0, 0, 0, 0};
    const float2* src = g_S2 + (size_t)bc * 16384;
    #pragma unroll 2
    for (int xx = 0; xx < 64; xx += 4) {
        float2 v0 = src[(xx+0)*256 + t];
        float2 v1 = src[(xx+1)*256 + t];
        float2 v2 = src[(xx+2)*256 + t];
        float2 v3 = src[(xx+3)*256 + t];
        ull sx0 = splat(v0.x), sy0 = splat(v0.y);
        ull sx1 = splat(v1.x), sy1 = splat(v1.y);
        ull sx2 = splat(v2.x), sy2 = splat(v2.y);
        ull sx3 = splat(v3.x), sy3 = splat(v3.y);
        #pragma unroll
        for (int i = 0; i < 4; i++) {
            int row = (kxg*4 + i)*64;
            acc[i] = ffma2(sx0, twA[row + xx],     acc[i]);
            acc[i] = ffma2(sy0, twB[row + xx],     acc[i]);
            acc[i] = ffma2(sx1, twA[row + xx + 1], acc[i]);
            acc[i] = ffma2(sy1, twB[row + xx + 1], acc[i]);
            acc[i] = ffma2(sx2, twA[row + xx + 2], acc[i]);
            acc[i] = ffma2(sy2, twB[row + xx + 2], acc[i]);
            acc[i] = ffma2(sx3, twA[row + xx + 3], acc[i]);
            acc[i] = ffma2(sy3, twB[row + xx + 3], acc[i]);
        }
    }
    float2* dst = g_XS + (size_t)bc * 4096;
    #pragma unroll
    for (int i = 0; i < 4; i++) dst[(kxg*4 + i)*256 + t] = upk(acc[i]);
}

// ---------------- K4: basis projection (4-way split, MLP-2) ----------------
__global__ void k4_proj() {
    __shared__ __align__(16) float2 sxs[4096];
    int bc = blockIdx.x >> 2;
    int p  = blockIdx.x & 3;
    int tid = threadIdx.x;           // 256
    const float4* srcv = (const float4*)&g_XS[(size_t)bc * 4096];
    for (int i = tid; i < 2048; i += 256) *(float4*)&sxs[i*2] = srcv[i];
    __syncthreads();
    if (tid < K144) {
        int k = tid;
        int s = k / 9, l = k - s * 9;
        int beg = g_off[s], end = g_off[s+1], len = end - beg;
        int i0 = beg + (len * p) / 4;
        int i1 = beg + (len * (p + 1)) / 4;
        ull acc0 = 0, acc1 = 0;
        int i = i0;
        for (; i + 2 <= i1; i += 2) {
            int m0 = g_sorted[i], m1 = g_sorted[i+1];
            float w0 = g_YWs[i*9 + l], w1 = g_YWs[(i+1)*9 + l];
            float2 u0 = sxs[m0], u1 = sxs[m1];
            acc0 = ffma2(splat(w0), pk(u0.x, u0.y), acc0);
            acc1 = ffma2(splat(w1), pk(u1.x, u1.y), acc1);
        }
        if (i < i1) {
            int m0 = g_sorted[i];
            float w0 = g_YWs[i*9 + l];
            float2 u0 = sxs[m0];
            acc0 = ffma2(splat(w0), pk(u0.x, u0.y), acc0);
        }
        float2 a = upk(acc0), bb = upk(acc1);
        g_C1P[((size_t)bc*4 + p)*K144 + k] = make_float2(a.x + bb.x, a.y + bb.y);
    }
}

// ---------------- K5: spectral conv fused with W1 ----------------
__global__ void k5_conv(const float* __restrict__ wr, const float* __restrict__ wi,
                        const float* __restrict__ w1r, const float* __restrict__ w1i) {
    __shared__ float2 cin[32];
    __shared__ float2 c2s[32];
    int blk = blockIdx.x;            // b*144 + sl
    int b = blk / K144, sl = blk - b * K144;
    int o = threadIdx.x;             // 32
    {
        size_t base = ((size_t)(b*32 + o))*4*K144 + sl;
        float2 a = g_C1P[base], bb = g_C1P[base + K144];
        float2 c = g_C1P[base + 2*K144], d = g_C1P[base + 3*K144];
        cin[o] = make_float2(a.x+bb.x+c.x+d.x, a.y+bb.y+c.y+d.y);
    }
    __syncwarp();
    const float* wrp = wr + (size_t)sl * 1024 + o;
    const float* wip = wi + (size_t)sl * 1024 + o;
    float ar = 0.f, ai = 0.f;
    #pragma unroll
    for (int i = 0; i < 32; i++) {
        float2 c = cin[i];
        float a = wrp[i*32], bb = wip[i*32];
        ar += c.x*a - c.y*bb;
        ai += c.x*bb + c.y*a;
    }
    const float invn = 1.0f / 262144.0f;
    c2s[o] = make_float2(ar*invn, ai*invn);
    __syncwarp();
    if (o < HID) {
        int j = o;
        float br = 0.f, bi = 0.f;
        #pragma unroll
        for (int q = 0; q < 32; q++) {
            float ax = w1r[j*32+q], ay = w1i[j*32+q];
            float2 c = c2s[q];
            br += ax*c.x - ay*c.y;
            bi += ax*c.y + ay*c.x;
        }
        g_C3[((size_t)(b*HID + j))*K144 + sl] = make_float2(br, bi);
    }
}

// ---------------- K67: inverse basis + inverse x/y-DFT ----------------
__global__ void k67_inv() {
    __shared__ ull c3[K144];
    __shared__ ull twiA[1024];       // (c, s)
    __shared__ ull twiB[1024];       // (-s, c)
    __shared__ float2 S[256];
    int bj = blockIdx.x >> 5;        // b*16 + j
    int xch = blockIdx.x & 31;
    int b = bj >> 4, j = bj & 15;
    int t = threadIdx.x;             // 256
    if (t < K144) {
        float2 v = g_C3[(size_t)bj*K144 + t];
        c3[t] = pk(v.x, v.y);
    }
    for (int i = t; i < 1024; i += 256) {
        int k = i >> 6, jj = i & 63;
        int fk = k < 8 ? k : k - 16;
        float2 w = g_TW[(jj * fk) & 63];
        twiA[i] = pk(w.x, w.y);
        twiB[i] = pk(-w.y, w.x);
    }
    __syncthreads();
    ull xs2[16];
    #pragma unroll
    for (int kx = 0; kx < 16; kx++) {
        int m = (kx << 8) | t;
        int s = g_shell[m];
        const float* yw = &g_YW[m*9];
        ull acc = 0;
        #pragma unroll
        for (int l = 0; l < 9; l++) acc = ffma2(splat(yw[l]), c3[s*9 + l], acc);
        xs2[kx] = acc;
    }
    for (int xi = 0; xi < 2; xi++) {
        int xx = xch * 2 + xi;
        ull o = 0;
        #pragma unroll
        for (int kx = 0; kx < 16; kx++) {
            float2 v = upk(xs2[kx]);
            o = ffma2(splat(v.x), twiA[kx*64 + xx], o);
            o = ffma2(splat(v.y), twiB[kx*64 + xx], o);
        }
        S[t] = upk(o);
        __syncthreads();
        {
            int y = t & 63, kzg = t >> 6;
            ull acc[4] = {0, 0, 0, 0};
            for (int ky = 0; ky < 16; ky++) {
                ull wA = twiA[ky*64 + y], wB = twiB[ky*64 + y];
                #pragma unroll
                for (int i = 0; i < 4; i++) {
                    float2 v = S[ky*16 + kzg*4 + i];
                    acc[i] = ffma2(splat(v.x), wA, acc[i]);
                    acc[i] = ffma2(splat(v.y), wB, acc[i]);
                }
            }
            size_t base = (((size_t)b*64 + xx)*64 + y)*256 + j*16 + kzg*4;
            #pragma unroll
            for (int i = 0; i < 4; i++) g_T2[base + i] = upk(acc[i]);
        }
        __syncthreads();
    }
}

// ---------------- K8: fused epilogue, 2-line blocks ----------------
__device__ __forceinline__ float gelu_t(float v) {
    float u = 0.7978845608028654f * (v + 0.044715f * v * v * v);
    float e = __expf(2.0f * u);
    float th = 1.0f - 2.0f / (e + 1.0f);
    return 0.5f * v * (1.0f + th);
}

#define K8_SMEM 37376

__global__ void __launch_bounds__(128, 5)
k8_final(const float* __restrict__ x,
         const float* __restrict__ wgr,
         const float* __restrict__ w2r, const float* __restrict__ w2i,
         const float* __restrict__ b2r,
         float* __restrict__ out) {
    extern __shared__ char sm[];
    float* s_x   = (float*)sm;               // [2][32][64] 16KB
    float* s_t2x = (float*)(sm + 16384);     // [2][16kz][16j] 2KB
    float* s_t2y = (float*)(sm + 18432);     // 2KB
    float* s_twc = (float*)(sm + 20480);     // [16kz][64z] 4KB
    float* s_tws = (float*)(sm + 24576);     // 4KB
    float* s_wcR = (float*)(sm + 28672);     // [32c][16j] 2KB
    float* s_wcI = (float*)(sm + 30720);     // 2KB
    float* s_w2r = (float*)(sm + 32768);     // [16j][32o] 2KB
    float* s_w2n = (float*)(sm + 34816);     // -w2i 2KB
    float* s_bcR = (float*)(sm + 36864);
    float* s_bcI = (float*)(sm + 36928);
    float* s_b2  = (float*)(sm + 36992);
    float* s_wg  = (float*)(sm + 37120);

    int blk = blockIdx.x;
    int b  = blk >> 11;
    int xc = (blk >> 5) & 63;
    int y0 = (blk & 31) * 2;
    int t = threadIdx.x;             // 128

    for (int i = t; i < 1024; i += 128) {
        int line = i >> 9, c = (i >> 4) & 31, zq = i & 15;
        float4 v = *(const float4*)&x[(((size_t)(b*32+c))*64 + xc)*4096 + (size_t)(y0+line)*64 + zq*4];
        *(float4*)&s_x[(line*32+c)*64 + zq*4] = v;
    }
    for (int i = t; i < 512; i += 128) {
        int line = i >> 8, q = i & 255;
        int j = q >> 4, kz = q & 15;
        float2 v = g_T2[((((size_t)b*64 + xc)*64) + (y0+line))*256 + q];
        s_t2x[(line*16 + kz)*16 + j] = v.x;
        s_t2y[(line*16 + kz)*16 + j] = v.y;
    }
    for (int i = t; i < 1024; i += 128) {
        int kz = i >> 6, z = i & 63;
        int fk = kz < 8 ? kz : kz - 16;
        float2 w = g_TW[(z*fk) & 63];
        s_twc[i] = w.x;
        s_tws[i] = w.y;
    }
    for (int i = t; i < 512; i += 128) {
        int c = i >> 4, j = i & 15;
        float2 wv = g_WC[j*32 + c];
        s_wcR[c*16 + j] = wv.x;
        s_wcI[c*16 + j] = wv.y;
        int jj = i >> 5, o = i & 31;
        s_w2r[jj*32 + o] = w2r[o*16 + jj];
        s_w2n[jj*32 + o] = -w2i[o*16 + jj];
    }
    if (t < 32) {
        s_b2[t] = b2r[t];
        s_wg[t] = wgr[t];
        if (t < 16) { float2 v = g_BC[t]; s_bcR[t] = v.x; s_bcI[t] = v.y; }
    }
    __syncthreads();

    int line = t >> 6, z = t & 63;
    const float* xl = &s_x[line*2048];

    // ---- pass 1: g = ifft_z(t2) + Wc*x + bc (packed over j-pairs) ----
    ull accR[8], accI[8];
    #pragma unroll
    for (int jp = 0; jp < 8; jp++) {
        accR[jp] = *(const ull*)&s_bcR[jp*2];
        accI[jp] = *(const ull*)&s_bcI[jp*2];
    }
    #pragma unroll
    for (int kz = 0; kz < 16; kz++) {
        float cw = s_twc[kz*64 + z], sw = s_tws[kz*64 + z];
        ull sc = splat(cw), ss = splat(sw), sn = splat(-sw);
        const ulonglong2* tx = (const ulonglong2*)&s_t2x[(line*16 + kz)*16];
        const ulonglong2* ty = (const ulonglong2*)&s_t2y[(line*16 + kz)*16];
        #pragma unroll
        for (int p = 0; p < 4; p++) {
            ulonglong2 a = tx[p], bv = ty[p];
            accR[2*p]   = ffma2(a.x,  sc, accR[2*p]);
            accR[2*p]   = ffma2(bv.x, sn, accR[2*p]);
            accI[2*p]   = ffma2(a.x,  ss, accI[2*p]);
            accI[2*p]   = ffma2(bv.x, sc, accI[2*p]);
            accR[2*p+1] = ffma2(a.y,  sc, accR[2*p+1]);
            accR[2*p+1] = ffma2(bv.y, sn, accR[2*p+1]);
            accI[2*p+1] = ffma2(a.y,  ss, accI[2*p+1]);
            accI[2*p+1] = ffma2(bv.y, sc, accI[2*p+1]);
        }
    }
    #pragma unroll 4
    for (int c = 0; c < 32; c++) {
        ull sx = splat(xl[c*64 + z]);
        const ulonglong2* wr = (const ulonglong2*)&s_wcR[c*16];
        const ulonglong2* wi = (const ulonglong2*)&s_wcI[c*16];
        #pragma unroll
        for (int p = 0; p < 4; p++) {
            ulonglong2 a = wr[p], bv = wi[p];
            accR[2*p]   = ffma2(a.x,  sx, accR[2*p]);
            accR[2*p+1] = ffma2(a.y,  sx, accR[2*p+1]);
            accI[2*p]   = ffma2(bv.x, sx, accI[2*p]);
            accI[2*p+1] = ffma2(bv.y, sx, accI[2*p+1]);
        }
    }

    // ---- gelu (h stays in registers) ----
    float hrf[16], hif[16];
    #pragma unroll
    for (int jp = 0; jp < 8; jp++) {
        float2 r  = upk(accR[jp]);
        float2 im = upk(accI[jp]);
        hrf[2*jp]   = gelu_t(r.x);
        hrf[2*jp+1] = gelu_t(r.y);
        hif[2*jp]   = gelu_t(im.x);
        hif[2*jp+1] = gelu_t(im.y);
    }

    // ---- pass 2: out = Re(W2 h) + b2 + x*wg, two o-halves ----
    int y = y0 + line;
    size_t obase = (((size_t)(b*32))*64 + xc)*4096 + (size_t)y*64 + z;
    #pragma unroll
    for (int h = 0; h < 2; h++) {
        ull accO[8];
        #pragma unroll
        for (int op = 0; op < 8; op++) {
            int o = h*16 + op*2;
            ull b2p = *(const ull*)&s_b2[o];
            ull wgp = *(const ull*)&s_wg[o];
            ull xp  = pk(xl[o*64 + z], xl[(o+1)*64 + z]);
            accO[op] = ffma2(xp, wgp, b2p);
        }
        #pragma unroll
        for (int j = 0; j < 16; j++) {
            ull shr = splat(hrf[j]), shi = splat(hif[j]);
            const ulonglong2* wr = (const ulonglong2*)&s_w2r[j*32 + h*16];
            const ulonglong2* wn = (const ulonglong2*)&s_w2n[j*32 + h*16];
            #pragma unroll
            for (int p = 0; p < 4; p++) {
                ulonglong2 a = wr[p], bv = wn[p];
                accO[2*p]   = ffma2(a.x,  shr, accO[2*p]);
                accO[2*p]   = ffma2(bv.x, shi, accO[2*p]);
                accO[2*p+1] = ffma2(a.y,  shr, accO[2*p+1]);
                accO[2*p+1] = ffma2(bv.y, shi, accO[2*p+1]);
            }
        }
        #pragma unroll
        for (int op = 0; op < 8; op++) {
            int o = h*16 + op*2;
            float2 v = upk(accO[op]);
            out[obase + (size_t)o     * 262144] = v.x;
            out[obase + (size_t)(o+1) * 262144] = v.y;
        }
    }
}

// ---------------- launch ----------------
extern "C" void kernel_launch(void* const* d_in, const int* in_sizes, int n_in,
                              void* d_out, int out_size) {
    const float* x    = (const float*)d_in[0];
    const float* wfr  = (const float*)d_in[1];
    const float* wfi  = (const float*)d_in[2];
    const float* bfr  = (const float*)d_in[3];
    const float* bfi  = (const float*)d_in[4];
    const float* wgr  = (const float*)d_in[5];
    const float* wsr  = (const float*)d_in[7];
    const float* wsi  = (const float*)d_in[8];
    const float* w1r  = (const float*)d_in[9];
    const float* w1i  = (const float*)d_in[10];
    const float* b1r  = (const float*)d_in[11];
    const float* b1i  = (const float*)d_in[12];
    const float* w2r  = (const float*)d_in[13];
    const float* w2i  = (const float*)d_in[14];
    const float* b2r  = (const float*)d_in[15];
    float* out = (float*)d_out;

    cudaFuncSetAttribute(k8_final, cudaFuncAttributeMaxDynamicSharedMemorySize, K8_SMEM);

    k0_init<<<1, 512>>>();
    kpre<<<1, 512>>>(wfr, wfi, bfr, bfi, w1r, w1i, b1r, b1i);
    k12_fwd<<<BB*CC*64, 256>>>(x);
    k3_xdft<<<BB*CC*4, 256>>>();
    k4_proj<<<BB*CC*4, 256>>>();
    k5_conv<<<BB*K144, 32>>>(wsr, wsi, w1r, w1i);
    k67_inv<<<BB*HID*32, 256>>>();
    k8_final<<<BB*64*32, 128, K8_SMEM>>>(x, wgr, w2r, w2i, b2r, out);
}

// round 7
// speedup vs baseline: 1.5399x; 1.2097x over previous
#include <cuda_runtime.h>
#include <math.h>

// ---------------- problem constants ----------------
#define BB 2
#define CC 32
#define HID 16
#define K144 144
#define M4096 4096

typedef unsigned long long ull;

// ---------------- packed f32x2 helpers ----------------
__device__ __forceinline__ ull pk(float lo, float hi) {
    ull r; asm("mov.b64 %0, {%1,%2};" : "=l"(r) : "f"(lo), "f"(hi)); return r;
}
__device__ __forceinline__ ull splat(float v) { return pk(v, v); }
__device__ __forceinline__ float2 upk(ull v) {
    float2 r; asm("mov.b64 {%0,%1}, %2;" : "=f"(r.x), "=f"(r.y) : "l"(v)); return r;
}
__device__ __forceinline__ ull ffma2(ull a, ull b, ull c) {
    ull d; asm("fma.rn.f32x2 %0, %1, %2, %3;" : "=l"(d) : "l"(a), "l"(b), "l"(c)); return d;
}
__device__ __forceinline__ ull add2(ull a, ull b) {
    ull d; asm("add.rn.f32x2 %0, %1, %2;" : "=l"(d) : "l"(a), "l"(b)); return d;
}

// ---------------- device scratch ----------------
__device__ __align__(16) float2 g_S2[BB*CC*64*256];
__device__ __align__(16) float2 g_XS[BB*CC*M4096];
__device__ __align__(16) float2 g_C1P[BB*CC*4*K144];
__device__ __align__(16) float2 g_C3[BB*HID*K144];
__device__ __align__(16) float2 g_T2[BB*64*64*256];
__device__ int    g_shell[M4096];
__device__ __align__(16) float g_YW[M4096*9];
__device__ __align__(16) float g_YWs[M4096*9];
__device__ int    g_sorted[M4096];
__device__ int    g_off[17];
__device__ float2 g_TW[64];
__device__ float2 g_WC[HID*CC];
__device__ float2 g_BC[HID];

// ---------------- K0a: per-mode tables (parallel) ----------------
__global__ void k0a_init() {
    int m = blockIdx.x * 128 + threadIdx.x;
    int ix = m >> 8, iy = (m >> 4) & 15, iz = m & 15;
    int fx = ix < 8 ? ix : ix - 16;
    int fy = iy < 8 ? iy : iy - 16;
    int fz = iz < 8 ? iz : iz - 16;
    int k2 = fx*fx + fy*fy + fz*fz;
    float rmax  = __fsqrt_rn(192.0f);
    float denom = __fadd_rn(rmax, 1e-6f);
    float r = __fsqrt_rn((float)k2);
    float q = __fmul_rn(__fdiv_rn(r, denom), 16.0f);
    int s = (int)q;
    if (s > 15) s = 15;
    g_shell[m] = s;
    float inv = (k2 > 0) ? __fdiv_rn(1.0f, r) : 0.0f;
    float ux = fx * inv, uy = fy * inv, uz = fz * inv;
    float nzm = k2 > 0 ? 1.0f : 0.0f;
    float* Y = &g_YW[m * 9];
    Y[0] = 0.282095f;
    Y[1] = 0.488603f * uy;
    Y[2] = 0.488603f * uz;
    Y[3] = 0.488603f * ux;
    Y[4] = 1.092548f * ux * uy;
    Y[5] = 1.092548f * uy * uz;
    Y[6] = 0.315392f * (3.0f * uz * uz - nzm);
    Y[7] = 1.092548f * ux * uz;
    Y[8] = 0.546274f * (ux * ux - uy * uy);
    if (blockIdx.x == 0 && threadIdx.x < 64) {
        int t = threadIdx.x;
        float ang = (float)(2.0 * M_PI * (double)t / 64.0);
        g_TW[t] = make_float2(cosf(ang), sinf(ang));
    }
}

// ---------------- K0b: per-shell deterministic sort + scale (16 blocks) ----------------
__global__ void k0b_sort() {
    int s = blockIdx.x;
    int t = threadIdx.x;                 // 256
    __shared__ int hist[16];
    __shared__ int chunkcnt[128];
    __shared__ int chunkpre[128];
    __shared__ float wSs;
    __shared__ int offs;
    if (t < 16) hist[t] = 0;
    __syncthreads();
    for (int i = t; i < M4096; i += 256) atomicAdd(&hist[g_shell[i]], 1);
    if (t < 128) {
        int c = 0;
        #pragma unroll 8
        for (int e = 0; e < 32; e++) c += (g_shell[t*32+e] == s) ? 1 : 0;
        chunkcnt[t] = c;
    }
    __syncthreads();
    if (t == 0) {
        int off = 0;
        for (int s2 = 0; s2 < s; s2++) off += hist[s2];
        offs = off;
        g_off[s] = off;
        if (s == 15) g_off[16] = off + hist[15];
        wSs = __fdiv_rn(1.0f, __fsqrt_rn(fmaxf((float)hist[s], 1.0f)));
        int acc = 0;
        for (int c = 0; c < 128; c++) { chunkpre[c] = acc; acc += chunkcnt[c]; }
    }
    __syncthreads();
    int w = t >> 5, lane = t & 31;
    float wS = wSs;
    int off0 = offs;
    for (int cc = w; cc < 128; cc += 8) {
        int m = cc*32 + lane;
        bool mine = (g_shell[m] == s);
        unsigned msk = __ballot_sync(0xffffffffu, mine);
        if (mine) {
            int p = off0 + chunkpre[cc] + __popc(msk & ((1u << lane) - 1u));
            g_sorted[p] = m;
            #pragma unroll
            for (int l = 0; l < 9; l++) {
                float v = g_YW[m*9+l] * wS;
                g_YWs[p*9+l] = v;
                g_YW[m*9+l]  = v;
            }
        }
    }
}

// ---------------- Kpre ----------------
__global__ void kpre(const float* __restrict__ wfr, const float* __restrict__ wfi,
                     const float* __restrict__ bfr, const float* __restrict__ bfi,
                     const float* __restrict__ w1r, const float* __restrict__ w1i,
                     const float* __restrict__ b1r, const float* __restrict__ b1i) {
    int t = threadIdx.x;                 // 512
    int j = t >> 5, c = t & 31;
    float ar = 0.f, ai = 0.f;
    for (int o = 0; o < 32; o++) {
        float ax = w1r[j*32+o], ay = w1i[j*32+o];
        float bx = wfr[o*32+c], by = wfi[o*32+c];
        ar += ax*bx - ay*by;
        ai += ax*by + ay*bx;
    }
    g_WC[j*32+c] = make_float2(ar, ai);
    if (c == 0) {
        float br = b1r[j], bi = b1i[j];
        for (int o = 0; o < 32; o++) {
            float ax = w1r[j*32+o], ay = w1i[j*32+o];
            float bx = bfr[o], by = bfi[o];
            br += ax*bx - ay*by;
            bi += ax*by + ay*bx;
        }
        g_BC[j] = make_float2(br, bi);
    }
}

// ---------------- K12: forward z-DFT (mirror fold) + y-DFT (half fold) ----------------
__global__ void k12_fwd(const float* __restrict__ x) {
    __shared__ __align__(16) float xp[64*68];
    __shared__ float2 S1[1024];
    __shared__ ull twA[16*33];     // (c,-s), cols 0..31
    __shared__ ull twB[16*33];     // (s, c)
    int blk = blockIdx.x;            // bc*64 + x
    int t = threadIdx.x;             // 256
    const float* src = x + (size_t)blk * 4096;
    for (int i = t; i < 1024; i += 256) {
        float4 v = *(const float4*)&src[i*4];
        int y = i >> 4, z0 = (i & 15) * 4;
        *(float4*)&xp[y*68 + z0] = v;
    }
    for (int i = t; i < 512; i += 256) {
        int k = i >> 5, j = i & 31;
        int fk = k < 8 ? k : k - 16;
        float2 w = g_TW[(j * fk) & 63];
        twA[k*33 + j] = pk(w.x, -w.y);
        twB[k*33 + j] = pk(w.y, w.x);
    }
    __syncthreads();
    // phase A: real z-DFT via z<->64-z mirror: (Re,Im) += (u,v) (x) (c,-s)
    {
        int y = t >> 2, q = t & 3;
        const float* row = &xp[y*68];
        float x0 = row[0], x32 = row[32];
        float sgn = (q & 1) ? -1.f : 1.f;
        ull a0 = pk(x0 + sgn*x32, 0.f);
        ull a1 = pk(x0 + sgn*x32, 0.f);
        ull a2 = pk(x0 + x32, 0.f);
        #pragma unroll 31
        for (int z = 1; z < 32; z++) {
            float fz = row[z], bz = row[64 - z];
            ull uv = pk(fz + bz, fz - bz);
            a0 = ffma2(uv, twA[q*33 + z], a0);
            a1 = ffma2(uv, twA[(q+4)*33 + z], a1);
            if (q == 0) a2 = ffma2(uv, twA[8*33 + z], a2);
        }
        float2 v0 = upk(a0), v1 = upk(a1), v2 = upk(a2);
        S1[y*16 + q]      = v0;
        S1[y*16 + q + 4]  = v1;
        S1[y*16 + 12 - q] = make_float2(v1.x, -v1.y);
        if (q > 0) S1[y*16 + 16 - q] = make_float2(v0.x, -v0.y);
        else       S1[y*16 + 8]      = v2;
    }
    __syncthreads();
    // phase B: complex y-DFT via y<->y+32 fold
    {
        int ky = t >> 4, kz = t & 15;
        ull sgnP = splat((ky & 1) ? -1.f : 1.f);
        ull acc = 0;
        #pragma unroll 4
        for (int y2 = 0; y2 < 32; y2++) {
            ull aU = *(const ull*)&S1[y2*16 + kz];
            ull bU = *(const ull*)&S1[(y2+32)*16 + kz];
            ull comb = ffma2(bU, sgnP, aU);
            float2 cb = upk(comb);
            acc = ffma2(splat(cb.x), twA[ky*33 + y2], acc);
            acc = ffma2(splat(cb.y), twB[ky*33 + y2], acc);
        }
        g_S2[(size_t)blk * 256 + t] = upk(acc);
    }
}

// ---------------- K3: forward x-DFT with x<->x+32 fold ----------------
__global__ void k3_xdft() {
    __shared__ ull twA[16*33];       // (c, -s), cols 0..31
    __shared__ ull twB[16*33];       // (s, c)
    int bc = blockIdx.x >> 2;
    int tq = blockIdx.x & 3;
    int tid = threadIdx.x;           // 256
    int kxg = tid >> 6, tl = tid & 63;
    int t = tq * 64 + tl;
    for (int i = tid; i < 512; i += 256) {
        int k = i >> 5, j = i & 31;
        int fk = k < 8 ? k : k - 16;
        float2 w = g_TW[(j * fk) & 63];
        twA[k*33 + j] = pk(w.x, -w.y);
        twB[k*33 + j] = pk(w.y, w.x);
    }
    __syncthreads();
    ull acc[4] = {0, 0, 0, 0};
    const float2* src = g_S2 + (size_t)bc * 16384;
    ull neg1 = splat(-1.f);
    #pragma unroll 4
    for (int xx = 0; xx < 32; xx++) {
        ull aU = *(const ull*)&src[xx*256 + t];
        ull bU = *(const ull*)&src[(xx+32)*256 + t];
        ull p = add2(aU, bU);
        ull mm = ffma2(bU, neg1, aU);
        float2 pp = upk(p), mv = upk(mm);
        ull px = splat(pp.x), py = splat(pp.y);
        ull mx = splat(mv.x), my = splat(mv.y);
        #pragma unroll
        for (int i = 0; i < 4; i++) {
            int row = (kxg*4 + i)*33 + xx;
            if (i & 1) {
                acc[i] = ffma2(mx, twA[row], acc[i]);
                acc[i] = ffma2(my, twB[row], acc[i]);
            } else {
                acc[i] = ffma2(px, twA[row], acc[i]);
                acc[i] = ffma2(py, twB[row], acc[i]);
            }
        }
    }
    float2* dst = g_XS + (size_t)bc * 4096;
    #pragma unroll
    for (int i = 0; i < 4; i++) dst[(kxg*4 + i)*256 + t] = upk(acc[i]);
}

// ---------------- K4: basis projection (4-way split, MLP-2) ----------------
__global__ void k4_proj() {
    __shared__ __align__(16) float2 sxs[4096];
    int bc = blockIdx.x >> 2;
    int p  = blockIdx.x & 3;
    int tid = threadIdx.x;           // 256
    const float4* srcv = (const float4*)&g_XS[(size_t)bc * 4096];
    for (int i = tid; i < 2048; i += 256) *(float4*)&sxs[i*2] = srcv[i];
    __syncthreads();
    if (tid < K144) {
        int k = tid;
        int s = k / 9, l = k - s * 9;
        int beg = g_off[s], end = g_off[s+1], len = end - beg;
        int i0 = beg + (len * p) / 4;
        int i1 = beg + (len * (p + 1)) / 4;
        ull acc0 = 0, acc1 = 0;
        int i = i0;
        for (; i + 2 <= i1; i += 2) {
            int m0 = g_sorted[i], m1 = g_sorted[i+1];
            float w0 = g_YWs[i*9 + l], w1 = g_YWs[(i+1)*9 + l];
            float2 u0 = sxs[m0], u1 = sxs[m1];
            acc0 = ffma2(splat(w0), pk(u0.x, u0.y), acc0);
            acc1 = ffma2(splat(w1), pk(u1.x, u1.y), acc1);
        }
        if (i < i1) {
            int m0 = g_sorted[i];
            float w0 = g_YWs[i*9 + l];
            float2 u0 = sxs[m0];
            acc0 = ffma2(splat(w0), pk(u0.x, u0.y), acc0);
        }
        float2 a = upk(acc0), bb = upk(acc1);
        g_C1P[((size_t)bc*4 + p)*K144 + k] = make_float2(a.x + bb.x, a.y + bb.y);
    }
}

// ---------------- K5: spectral conv fused with W1 ----------------
__global__ void k5_conv(const float* __restrict__ wr, const float* __restrict__ wi,
                        const float* __restrict__ w1r, const float* __restrict__ w1i) {
    __shared__ float2 cin[32];
    __shared__ float2 c2s[32];
    int blk = blockIdx.x;            // b*144 + sl
    int b = blk / K144, sl = blk - b * K144;
    int o = threadIdx.x;             // 32
    {
        size_t base = ((size_t)(b*32 + o))*4*K144 + sl;
        float2 a = g_C1P[base], bb = g_C1P[base + K144];
        float2 c = g_C1P[base + 2*K144], d = g_C1P[base + 3*K144];
        cin[o] = make_float2(a.x+bb.x+c.x+d.x, a.y+bb.y+c.y+d.y);
    }
    __syncwarp();
    const float* wrp = wr + (size_t)sl * 1024 + o;
    const float* wip = wi + (size_t)sl * 1024 + o;
    float ar = 0.f, ai = 0.f;
    #pragma unroll
    for (int i = 0; i < 32; i++) {
        float2 c = cin[i];
        float a = wrp[i*32], bb = wip[i*32];
        ar += c.x*a - c.y*bb;
        ai += c.x*bb + c.y*a;
    }
    const float invn = 1.0f / 262144.0f;
    c2s[o] = make_float2(ar*invn, ai*invn);
    __syncwarp();
    if (o < HID) {
        int j = o;
        float br = 0.f, bi = 0.f;
        #pragma unroll
        for (int q = 0; q < 32; q++) {
            float ax = w1r[j*32+q], ay = w1i[j*32+q];
            float2 c = c2s[q];
            br += ax*c.x - ay*c.y;
            bi += ax*c.y + ay*c.x;
        }
        g_C3[((size_t)(b*HID + j))*K144 + sl] = make_float2(br, bi);
    }
}

// ---------------- K67: inverse basis + inverse x/y-DFT (E/O output fold) ----------------
__global__ void k67_inv() {
    __shared__ ull c3[K144];
    __shared__ ull twiA[16*33];      // (c, s), cols 0..31
    __shared__ ull twiB[16*33];      // (-s, c)
    __shared__ float2 SA[256];       // xx = xl
    __shared__ float2 SB[256];       // xx = xl + 32
    int bj = blockIdx.x >> 5;        // b*16 + j
    int xl = blockIdx.x & 31;
    int b = bj >> 4, j = bj & 15;
    int t = threadIdx.x;             // 256
    if (t < K144) {
        float2 v = g_C3[(size_t)bj*K144 + t];
        c3[t] = pk(v.x, v.y);
    }
    for (int i = t; i < 512; i += 256) {
        int k = i >> 5, col = i & 31;
        int fk = k < 8 ? k : k - 16;
        float2 w = g_TW[(col * fk) & 63];
        twiA[k*33 + col] = pk(w.x, w.y);
        twiB[k*33 + col] = pk(-w.y, w.x);
    }
    __syncthreads();
    // inverse basis: xs2[kx] for t = ky*16+kz
    ull xs2[16];
    #pragma unroll
    for (int kx = 0; kx < 16; kx++) {
        int m = (kx << 8) | t;
        int s = g_shell[m];
        const float* yw = &g_YW[m*9];
        ull acc = 0;
        #pragma unroll
        for (int l = 0; l < 9; l++) acc = ffma2(splat(yw[l]), c3[s*9 + l], acc);
        xs2[kx] = acc;
    }
    ull neg1 = splat(-1.f);
    // x-stage: out(xl) = E+O, out(xl+32) = E-O
    {
        ull E = 0, O = 0;
        #pragma unroll
        for (int kx = 0; kx < 16; kx++) {
            float2 v = upk(xs2[kx]);
            ull wA = twiA[kx*33 + xl], wB = twiB[kx*33 + xl];
            if (kx & 1) {
                O = ffma2(splat(v.x), wA, O);
                O = ffma2(splat(v.y), wB, O);
            } else {
                E = ffma2(splat(v.x), wA, E);
                E = ffma2(splat(v.y), wB, E);
            }
        }
        SA[t] = upk(add2(E, O));
        SB[t] = upk(ffma2(O, neg1, E));
    }
    __syncthreads();
    // y-stage: thread = (yp 0..31, kzq 0..7); outputs y=yp and y=yp+32, kz pair
    int yp = t >> 3;
    int kzq = t & 7;
    #pragma unroll
    for (int xi = 0; xi < 2; xi++) {
        const float2* S = xi ? SB : SA;
        int xx = xl + 32*xi;
        float2 r0[2], r1[2];
        #pragma unroll
        for (int k2 = 0; k2 < 2; k2++) {
            int kz = kzq*2 + k2;
            ull E = 0, O = 0;
            #pragma unroll
            for (int ky = 0; ky < 16; ky++) {
                float2 v = S[ky*16 + kz];
                ull wA = twiA[ky*33 + yp], wB = twiB[ky*33 + yp];
                if (ky & 1) {
                    O = ffma2(splat(v.x), wA, O);
                    O = ffma2(splat(v.y), wB, O);
                } else {
                    E = ffma2(splat(v.x), wA, E);
                    E = ffma2(splat(v.y), wB, E);
                }
            }
            r0[k2] = upk(add2(E, O));
            r1[k2] = upk(ffma2(O, neg1, E));
        }
        size_t base = ((size_t)b*64 + xx)*64;
        float4 w0 = make_float4(r0[0].x, r0[0].y, r0[1].x, r0[1].y);
        float4 w1 = make_float4(r1[0].x, r1[0].y, r1[1].x, r1[1].y);
        *(float4*)&g_T2[(base + yp)*256 + j*16 + kzq*2]      = w0;
        *(float4*)&g_T2[(base + yp + 32)*256 + j*16 + kzq*2] = w1;
    }
}

// ---------------- K8: fused epilogue (unchanged from R5) ----------------
__device__ __forceinline__ float gelu_t(float v) {
    float u = 0.7978845608028654f * (v + 0.044715f * v * v * v);
    float e = __expf(2.0f * u);
    float th = 1.0f - 2.0f / (e + 1.0f);
    return 0.5f * v * (1.0f + th);
}

#define K8_SMEM 37376

__global__ void __launch_bounds__(128, 5)
k8_final(const float* __restrict__ x,
         const float* __restrict__ wgr,
         const float* __restrict__ w2r, const float* __restrict__ w2i,
         const float* __restrict__ b2r,
         float* __restrict__ out) {
    extern __shared__ char sm[];
    float* s_x   = (float*)sm;
    float* s_t2x = (float*)(sm + 16384);
    float* s_t2y = (float*)(sm + 18432);
    float* s_twc = (float*)(sm + 20480);
    float* s_tws = (float*)(sm + 24576);
    float* s_wcR = (float*)(sm + 28672);
    float* s_wcI = (float*)(sm + 30720);
    float* s_w2r = (float*)(sm + 32768);
    float* s_w2n = (float*)(sm + 34816);
    float* s_bcR = (float*)(sm + 36864);
    float* s_bcI = (float*)(sm + 36928);
    float* s_b2  = (float*)(sm + 36992);
    float* s_wg  = (float*)(sm + 37120);

    int blk = blockIdx.x;
    int b  = blk >> 11;
    int xc = (blk >> 5) & 63;
    int y0 = (blk & 31) * 2;
    int t = threadIdx.x;             // 128

    for (int i = t; i < 1024; i += 128) {
        int line = i >> 9, c = (i >> 4) & 31, zq = i & 15;
        float4 v = *(const float4*)&x[(((size_t)(b*32+c))*64 + xc)*4096 + (size_t)(y0+line)*64 + zq*4];
        *(float4*)&s_x[(line*32+c)*64 + zq*4] = v;
    }
    for (int i = t; i < 512; i += 128) {
        int line = i >> 8, q = i & 255;
        int j = q >> 4, kz = q & 15;
        float2 v = g_T2[((((size_t)b*64 + xc)*64) + (y0+line))*256 + q];
        s_t2x[(line*16 + kz)*16 + j] = v.x;
        s_t2y[(line*16 + kz)*16 + j] = v.y;
    }
    for (int i = t; i < 1024; i += 128) {
        int kz = i >> 6, z = i & 63;
        int fk = kz < 8 ? kz : kz - 16;
        float2 w = g_TW[(z*fk) & 63];
        s_twc[i] = w.x;
        s_tws[i] = w.y;
    }
    for (int i = t; i < 512; i += 128) {
        int c = i >> 4, j = i & 15;
        float2 wv = g_WC[j*32 + c];
        s_wcR[c*16 + j] = wv.x;
        s_wcI[c*16 + j] = wv.y;
        int jj = i >> 5, o = i & 31;
        s_w2r[jj*32 + o] = w2r[o*16 + jj];
        s_w2n[jj*32 + o] = -w2i[o*16 + jj];
    }
    if (t < 32) {
        s_b2[t] = b2r[t];
        s_wg[t] = wgr[t];
        if (t < 16) { float2 v = g_BC[t]; s_bcR[t] = v.x; s_bcI[t] = v.y; }
    }
    __syncthreads();

    int line = t >> 6, z = t & 63;
    const float* xl = &s_x[line*2048];

    ull accR[8], accI[8];
    #pragma unroll
    for (int jp = 0; jp < 8; jp++) {
        accR[jp] = *(const ull*)&s_bcR[jp*2];
        accI[jp] = *(const ull*)&s_bcI[jp*2];
    }
    #pragma unroll
    for (int kz = 0; kz < 16; kz++) {
        float cw = s_twc[kz*64 + z], sw = s_tws[kz*64 + z];
        ull sc = splat(cw), ss = splat(sw), sn = splat(-sw);
        const ulonglong2* tx = (const ulonglong2*)&s_t2x[(line*16 + kz)*16];
        const ulonglong2* ty = (const ulonglong2*)&s_t2y[(line*16 + kz)*16];
        #pragma unroll
        for (int p = 0; p < 4; p++) {
            ulonglong2 a = tx[p], bv = ty[p];
            accR[2*p]   = ffma2(a.x,  sc, accR[2*p]);
            accR[2*p]   = ffma2(bv.x, sn, accR[2*p]);
            accI[2*p]   = ffma2(a.x,  ss, accI[2*p]);
            accI[2*p]   = ffma2(bv.x, sc, accI[2*p]);
            accR[2*p+1] = ffma2(a.y,  sc, accR[2*p+1]);
            accR[2*p+1] = ffma2(bv.y, sn, accR[2*p+1]);
            accI[2*p+1] = ffma2(a.y,  ss, accI[2*p+1]);
            accI[2*p+1] = ffma2(bv.y, sc, accI[2*p+1]);
        }
    }
    #pragma unroll 4
    for (int c = 0; c < 32; c++) {
        ull sx = splat(xl[c*64 + z]);
        const ulonglong2* wr = (const ulonglong2*)&s_wcR[c*16];
        const ulonglong2* wi = (const ulonglong2*)&s_wcI[c*16];
        #pragma unroll
        for (int p = 0; p < 4; p++) {
            ulonglong2 a = wr[p], bv = wi[p];
            accR[2*p]   = ffma2(a.x,  sx, accR[2*p]);
            accR[2*p+1] = ffma2(a.y,  sx, accR[2*p+1]);
            accI[2*p]   = ffma2(bv.x, sx, accI[2*p]);
            accI[2*p+1] = ffma2(bv.y, sx, accI[2*p+1]);
        }
    }

    float hrf[16], hif[16];
    #pragma unroll
    for (int jp = 0; jp < 8; jp++) {
        float2 r  = upk(accR[jp]);
        float2 im = upk(accI[jp]);
        hrf[2*jp]   = gelu_t(r.x);
        hrf[2*jp+1] = gelu_t(r.y);
        hif[2*jp]   = gelu_t(im.x);
        hif[2*jp+1] = gelu_t(im.y);
    }

    int y = y0 + line;
    size_t obase = (((size_t)(b*32))*64 + xc)*4096 + (size_t)y*64 + z;
    #pragma unroll
    for (int h = 0; h < 2; h++) {
        ull accO[8];
        #pragma unroll
        for (int op = 0; op < 8; op++) {
            int o = h*16 + op*2;
            ull b2p = *(const ull*)&s_b2[o];
            ull wgp = *(const ull*)&s_wg[o];
            ull xp  = pk(xl[o*64 + z], xl[(o+1)*64 + z]);
            accO[op] = ffma2(xp, wgp, b2p);
        }
        #pragma unroll
        for (int j = 0; j < 16; j++) {
            ull shr = splat(hrf[j]), shi = splat(hif[j]);
            const ulonglong2* wr = (const ulonglong2*)&s_w2r[j*32 + h*16];
            const ulonglong2* wn = (const ulonglong2*)&s_w2n[j*32 + h*16];
            #pragma unroll
            for (int p = 0; p < 4; p++) {
                ulonglong2 a = wr[p], bv = wn[p];
                accO[2*p]   = ffma2(a.x,  shr, accO[2*p]);
                accO[2*p]   = ffma2(bv.x, shi, accO[2*p]);
                accO[2*p+1] = ffma2(a.y,  shr, accO[2*p+1]);
                accO[2*p+1] = ffma2(bv.y, shi, accO[2*p+1]);
            }
        }
        #pragma unroll
        for (int op = 0; op < 8; op++) {
            int o = h*16 + op*2;
            float2 v = upk(accO[op]);
            out[obase + (size_t)o     * 262144] = v.x;
            out[obase + (size_t)(o+1) * 262144] = v.y;
        }
    }
}

// ---------------- launch ----------------
extern "C" void kernel_launch(void* const* d_in, const int* in_sizes, int n_in,
                              void* d_out, int out_size) {
    const float* x    = (const float*)d_in[0];
    const float* wfr  = (const float*)d_in[1];
    const float* wfi  = (const float*)d_in[2];
    const float* bfr  = (const float*)d_in[3];
    const float* bfi  = (const float*)d_in[4];
    const float* wgr  = (const float*)d_in[5];
    const float* wsr  = (const float*)d_in[7];
    const float* wsi  = (const float*)d_in[8];
    const float* w1r  = (const float*)d_in[9];
    const float* w1i  = (const float*)d_in[10];
    const float* b1r  = (const float*)d_in[11];
    const float* b1i  = (const float*)d_in[12];
    const float* w2r  = (const float*)d_in[13];
    const float* w2i  = (const float*)d_in[14];
    const float* b2r  = (const float*)d_in[15];
    float* out = (float*)d_out;

    cudaFuncSetAttribute(k8_final, cudaFuncAttributeMaxDynamicSharedMemorySize, K8_SMEM);

    k0a_init<<<32, 128>>>();
    k0b_sort<<<16, 256>>>();
    kpre<<<1, 512>>>(wfr, wfi, bfr, bfi, w1r, w1i, b1r, b1i);
    k12_fwd<<<BB*CC*64, 256>>>(x);
    k3_xdft<<<BB*CC*4, 256>>>();
    k4_proj<<<BB*CC*4, 256>>>();
    k5_conv<<<BB*K144, 32>>>(wsr, wsi, w1r, w1i);
    k67_inv<<<BB*HID*32, 256>>>();
    k8_final<<<BB*64*32, 128, K8_SMEM>>>(x, wgr, w2r, w2i, b2r, out);
}

// round 8
// speedup vs baseline: 1.8819x; 1.2221x over previous
#include <cuda_runtime.h>
#include <math.h>

// ---------------- problem constants ----------------
#define BB 2
#define CC 32
#define HID 16
#define K144 144
#define M4096 4096

typedef unsigned long long ull;

// ---------------- packed f32x2 helpers ----------------
__device__ __forceinline__ ull pk(float lo, float hi) {
    ull r; asm("mov.b64 %0, {%1,%2};" : "=l"(r) : "f"(lo), "f"(hi)); return r;
}
__device__ __forceinline__ ull splat(float v) { return pk(v, v); }
__device__ __forceinline__ float2 upk(ull v) {
    float2 r; asm("mov.b64 {%0,%1}, %2;" : "=f"(r.x), "=f"(r.y) : "l"(v)); return r;
}
__device__ __forceinline__ ull ffma2(ull a, ull b, ull c) {
    ull d; asm("fma.rn.f32x2 %0, %1, %2, %3;" : "=l"(d) : "l"(a), "l"(b), "l"(c)); return d;
}
__device__ __forceinline__ ull add2(ull a, ull b) {
    ull d; asm("add.rn.f32x2 %0, %1, %2;" : "=l"(d) : "l"(a), "l"(b)); return d;
}

// ---------------- device scratch ----------------
__device__ __align__(16) float2 g_S2[BB*CC*64*256];
__device__ __align__(16) float2 g_XS[BB*CC*M4096];
__device__ __align__(16) float2 g_C1P[BB*CC*4*K144];
__device__ __align__(16) float2 g_C3[BB*HID*K144];
__device__ __align__(16) float2 g_T2[BB*64*64*256];
__device__ int    g_shell[M4096];
__device__ __align__(16) float g_YW[M4096*9];      // unscaled, [m][l] (k0a output)
__device__ __align__(16) float g_YWT[9*M4096];     // scaled, [l][m]   (k67)
__device__ __align__(16) float g_YWsT[9*M4096];    // scaled, [l][sorted p] (k4)
__device__ int    g_sorted[M4096];
__device__ int    g_off[17];
__device__ float2 g_TW[64];
__device__ float2 g_WC[HID*CC];
__device__ float2 g_BC[HID];

// ---------------- K0a: per-mode tables (parallel) ----------------
__global__ void k0a_init() {
    int m = blockIdx.x * 128 + threadIdx.x;
    int ix = m >> 8, iy = (m >> 4) & 15, iz = m & 15;
    int fx = ix < 8 ? ix : ix - 16;
    int fy = iy < 8 ? iy : iy - 16;
    int fz = iz < 8 ? iz : iz - 16;
    int k2 = fx*fx + fy*fy + fz*fz;
    float rmax  = __fsqrt_rn(192.0f);
    float denom = __fadd_rn(rmax, 1e-6f);
    float r = __fsqrt_rn((float)k2);
    float q = __fmul_rn(__fdiv_rn(r, denom), 16.0f);
    int s = (int)q;
    if (s > 15) s = 15;
    g_shell[m] = s;
    float inv = (k2 > 0) ? __fdiv_rn(1.0f, r) : 0.0f;
    float ux = fx * inv, uy = fy * inv, uz = fz * inv;
    float nzm = k2 > 0 ? 1.0f : 0.0f;
    float* Y = &g_YW[m * 9];
    Y[0] = 0.282095f;
    Y[1] = 0.488603f * uy;
    Y[2] = 0.488603f * uz;
    Y[3] = 0.488603f * ux;
    Y[4] = 1.092548f * ux * uy;
    Y[5] = 1.092548f * uy * uz;
    Y[6] = 0.315392f * (3.0f * uz * uz - nzm);
    Y[7] = 1.092548f * ux * uz;
    Y[8] = 0.546274f * (ux * ux - uy * uy);
    if (blockIdx.x == 0 && threadIdx.x < 64) {
        int t = threadIdx.x;
        float ang = (float)(2.0 * M_PI * (double)t / 64.0);
        g_TW[t] = make_float2(cosf(ang), sinf(ang));
    }
}

// ---------------- K0b: per-shell deterministic sort + scaled transposed tables ----------------
__global__ void k0b_sort() {
    int s = blockIdx.x;
    int t = threadIdx.x;                 // 256
    __shared__ int hist[16];
    __shared__ int chunkcnt[128];
    __shared__ int chunkpre[128];
    __shared__ float wSs;
    __shared__ int offs;
    if (t < 16) hist[t] = 0;
    __syncthreads();
    for (int i = t; i < M4096; i += 256) atomicAdd(&hist[g_shell[i]], 1);
    if (t < 128) {
        int c = 0;
        #pragma unroll 8
        for (int e = 0; e < 32; e++) c += (g_shell[t*32+e] == s) ? 1 : 0;
        chunkcnt[t] = c;
    }
    __syncthreads();
    if (t == 0) {
        int off = 0;
        for (int s2 = 0; s2 < s; s2++) off += hist[s2];
        offs = off;
        g_off[s] = off;
        if (s == 15) g_off[16] = off + hist[15];
        wSs = __fdiv_rn(1.0f, __fsqrt_rn(fmaxf((float)hist[s], 1.0f)));
        int acc = 0;
        for (int c = 0; c < 128; c++) { chunkpre[c] = acc; acc += chunkcnt[c]; }
    }
    __syncthreads();
    int w = t >> 5, lane = t & 31;
    float wS = wSs;
    int off0 = offs;
    for (int cc = w; cc < 128; cc += 8) {
        int m = cc*32 + lane;
        bool mine = (g_shell[m] == s);
        unsigned msk = __ballot_sync(0xffffffffu, mine);
        if (mine) {
            int p = off0 + chunkpre[cc] + __popc(msk & ((1u << lane) - 1u));
            g_sorted[p] = m;
            #pragma unroll
            for (int l = 0; l < 9; l++) {
                float v = g_YW[m*9+l] * wS;
                g_YWT[l*M4096 + m]  = v;
                g_YWsT[l*M4096 + p] = v;
            }
        }
    }
}

// ---------------- Kpre ----------------
__global__ void kpre(const float* __restrict__ wfr, const float* __restrict__ wfi,
                     const float* __restrict__ bfr, const float* __restrict__ bfi,
                     const float* __restrict__ w1r, const float* __restrict__ w1i,
                     const float* __restrict__ b1r, const float* __restrict__ b1i) {
    int t = threadIdx.x;                 // 512
    int j = t >> 5, c = t & 31;
    float ar = 0.f, ai = 0.f;
    for (int o = 0; o < 32; o++) {
        float ax = w1r[j*32+o], ay = w1i[j*32+o];
        float bx = wfr[o*32+c], by = wfi[o*32+c];
        ar += ax*bx - ay*by;
        ai += ax*by + ay*bx;
    }
    g_WC[j*32+c] = make_float2(ar, ai);
    if (c == 0) {
        float br = b1r[j], bi = b1i[j];
        for (int o = 0; o < 32; o++) {
            float ax = w1r[j*32+o], ay = w1i[j*32+o];
            float bx = bfr[o], by = bfi[o];
            br += ax*bx - ay*by;
            bi += ax*by + ay*bx;
        }
        g_BC[j] = make_float2(br, bi);
    }
}

// ---------------- K12: forward z-DFT (double fold) + y-DFT (half fold) ----------------
__global__ void k12_fwd(const float* __restrict__ x) {
    __shared__ __align__(16) float xp[64*68];
    __shared__ float2 S1[1024];
    __shared__ ull twA[16*33];     // (c,-s), cols 0..32
    __shared__ ull twB[16*33];     // (s, c)
    int blk = blockIdx.x;            // bc*64 + x
    int t = threadIdx.x;             // 256
    const float* src = x + (size_t)blk * 4096;
    for (int i = t; i < 1024; i += 256) {
        float4 v = *(const float4*)&src[i*4];
        int y = i >> 4, z0 = (i & 15) * 4;
        *(float4*)&xp[y*68 + z0] = v;
    }
    for (int i = t; i < 528; i += 256) {
        int k = i / 33, j = i - k*33;
        int fk = k < 8 ? k : k - 16;
        float2 w = g_TW[(j * fk) & 63];
        twA[k*33 + j] = pk(w.x, -w.y);
        twB[k*33 + j] = pk(w.y, w.x);
    }
    __syncthreads();
    // phase A: real z-DFT double fold (z<->64-z then z<->32-z)
    {
        int y = t >> 2, q = t & 3;
        const float* row = &xp[y*68];
        float x0 = row[0], x32v = row[32];
        float sgn = (q & 1) ? -1.f : 1.f;
        ull sgnP = splat(sgn);
        ull a0 = pk(x0 + sgn*x32v, 0.f);
        ull a1 = a0;
        ull a2 = pk(x0 + x32v, 0.f);
        #pragma unroll
        for (int z = 1; z <= 15; z++) {
            float xa = row[z],      xb = row[64 - z];
            float xc = row[32 - z], xd = row[32 + z];
            float p  = xa + xb, md = xa - xb;
            float r  = xc + xd, td = xc - xd;
            ull base = pk(p, md);
            ull alt  = pk(r, -td);
            ull uvE  = add2(base, alt);           // even-fk combo
            ull uvQ  = ffma2(alt, sgnP, base);    // parity-of-q combo
            a2 = ffma2(uvE, twA[8*33 + z], a2);
            a0 = ffma2(uvQ, twA[q*33 + z], a0);
            a1 = ffma2(uvQ, twA[(q+4)*33 + z], a1);
        }
        {   // z = 16 (self-paired)
            float xa = row[16], xb = row[48];
            ull uv16 = pk(xa + xb, xa - xb);
            a0 = ffma2(uv16, twA[q*33 + 16], a0);
            a1 = ffma2(uv16, twA[(q+4)*33 + 16], a1);
            a2 = ffma2(uv16, twA[8*33 + 16], a2);
        }
        float2 v0 = upk(a0), v1 = upk(a1), v2 = upk(a2);
        S1[y*16 + q]      = v0;
        S1[y*16 + q + 4]  = v1;
        S1[y*16 + 12 - q] = make_float2(v1.x, -v1.y);
        if (q > 0) S1[y*16 + 16 - q] = make_float2(v0.x, -v0.y);
        else       S1[y*16 + 8]      = v2;
    }
    __syncthreads();
    // phase B: complex y-DFT via y<->y+32 fold
    {
        int ky = t >> 4, kz = t & 15;
        ull sgnP = splat((ky & 1) ? -1.f : 1.f);
        ull acc = 0;
        #pragma unroll 4
        for (int y2 = 0; y2 < 32; y2++) {
            ull aU = *(const ull*)&S1[y2*16 + kz];
            ull bU = *(const ull*)&S1[(y2+32)*16 + kz];
            ull comb = ffma2(bU, sgnP, aU);
            float2 cb = upk(comb);
            acc = ffma2(splat(cb.x), twA[ky*33 + y2], acc);
            acc = ffma2(splat(cb.y), twB[ky*33 + y2], acc);
        }
        g_S2[(size_t)blk * 256 + t] = upk(acc);
    }
}

// ---------------- K3: forward x-DFT with x<->x+32 fold ----------------
__global__ void k3_xdft() {
    __shared__ ull twA[16*33];       // (c, -s), cols 0..31
    __shared__ ull twB[16*33];       // (s, c)
    int bc = blockIdx.x >> 2;
    int tq = blockIdx.x & 3;
    int tid = threadIdx.x;           // 256
    int kxg = tid >> 6, tl = tid & 63;
    int t = tq * 64 + tl;
    for (int i = tid; i < 512; i += 256) {
        int k = i >> 5, j = i & 31;
        int fk = k < 8 ? k : k - 16;
        float2 w = g_TW[(j * fk) & 63];
        twA[k*33 + j] = pk(w.x, -w.y);
        twB[k*33 + j] = pk(w.y, w.x);
    }
    __syncthreads();
    ull acc[4] = {0, 0, 0, 0};
    const float2* src = g_S2 + (size_t)bc * 16384;
    ull neg1 = splat(-1.f);
    #pragma unroll 4
    for (int xx = 0; xx < 32; xx++) {
        ull aU = *(const ull*)&src[xx*256 + t];
        ull bU = *(const ull*)&src[(xx+32)*256 + t];
        ull p = add2(aU, bU);
        ull mm = ffma2(bU, neg1, aU);
        float2 pp = upk(p), mv = upk(mm);
        ull px = splat(pp.x), py = splat(pp.y);
        ull mx = splat(mv.x), my = splat(mv.y);
        #pragma unroll
        for (int i = 0; i < 4; i++) {
            int row = (kxg*4 + i)*33 + xx;
            if (i & 1) {
                acc[i] = ffma2(mx, twA[row], acc[i]);
                acc[i] = ffma2(my, twB[row], acc[i]);
            } else {
                acc[i] = ffma2(px, twA[row], acc[i]);
                acc[i] = ffma2(py, twB[row], acc[i]);
            }
        }
    }
    float2* dst = g_XS + (size_t)bc * 4096;
    #pragma unroll
    for (int i = 0; i < 4; i++) dst[(kxg*4 + i)*256 + t] = upk(acc[i]);
}

// ---------------- K4: basis projection (transposed table) ----------------
__global__ void k4_proj() {
    __shared__ __align__(16) float2 sxs[4096];
    int bc = blockIdx.x >> 2;
    int p  = blockIdx.x & 3;
    int tid = threadIdx.x;           // 256
    const float4* srcv = (const float4*)&g_XS[(size_t)bc * 4096];
    for (int i = tid; i < 2048; i += 256) *(float4*)&sxs[i*2] = srcv[i];
    __syncthreads();
    if (tid < K144) {
        int k = tid;
        int s = k / 9, l = k - s * 9;
        const float* ywp = &g_YWsT[l*M4096];
        int beg = g_off[s], end = g_off[s+1], len = end - beg;
        int i0 = beg + (len * p) / 4;
        int i1 = beg + (len * (p + 1)) / 4;
        ull acc0 = 0, acc1 = 0;
        int i = i0;
        for (; i + 2 <= i1; i += 2) {
            int m0 = g_sorted[i], m1 = g_sorted[i+1];
            float w0 = ywp[i], w1 = ywp[i+1];
            float2 u0 = sxs[m0], u1 = sxs[m1];
            acc0 = ffma2(splat(w0), pk(u0.x, u0.y), acc0);
            acc1 = ffma2(splat(w1), pk(u1.x, u1.y), acc1);
        }
        if (i < i1) {
            int m0 = g_sorted[i];
            float w0 = ywp[i];
            float2 u0 = sxs[m0];
            acc0 = ffma2(splat(w0), pk(u0.x, u0.y), acc0);
        }
        float2 a = upk(acc0), bb = upk(acc1);
        g_C1P[((size_t)bc*4 + p)*K144 + k] = make_float2(a.x + bb.x, a.y + bb.y);
    }
}

// ---------------- K5: spectral conv fused with W1 ----------------
__global__ void k5_conv(const float* __restrict__ wr, const float* __restrict__ wi,
                        const float* __restrict__ w1r, const float* __restrict__ w1i) {
    __shared__ float2 cin[32];
    __shared__ float2 c2s[32];
    int blk = blockIdx.x;            // b*144 + sl
    int b = blk / K144, sl = blk - b * K144;
    int o = threadIdx.x;             // 32
    {
        size_t base = ((size_t)(b*32 + o))*4*K144 + sl;
        float2 a = g_C1P[base], bb = g_C1P[base + K144];
        float2 c = g_C1P[base + 2*K144], d = g_C1P[base + 3*K144];
        cin[o] = make_float2(a.x+bb.x+c.x+d.x, a.y+bb.y+c.y+d.y);
    }
    __syncwarp();
    const float* wrp = wr + (size_t)sl * 1024 + o;
    const float* wip = wi + (size_t)sl * 1024 + o;
    float ar = 0.f, ai = 0.f;
    #pragma unroll
    for (int i = 0; i < 32; i++) {
        float2 c = cin[i];
        float a = wrp[i*32], bb = wip[i*32];
        ar += c.x*a - c.y*bb;
        ai += c.x*bb + c.y*a;
    }
    const float invn = 1.0f / 262144.0f;
    c2s[o] = make_float2(ar*invn, ai*invn);
    __syncwarp();
    if (o < HID) {
        int j = o;
        float br = 0.f, bi = 0.f;
        #pragma unroll
        for (int q = 0; q < 32; q++) {
            float ax = w1r[j*32+q], ay = w1i[j*32+q];
            float2 c = c2s[q];
            br += ax*c.x - ay*c.y;
            bi += ax*c.y + ay*c.x;
        }
        g_C3[((size_t)(b*HID + j))*K144 + sl] = make_float2(br, bi);
    }
}

// ---------------- K67: inverse basis (transposed, coalesced) + inverse x/y-DFT ----------------
__global__ void k67_inv() {
    __shared__ ull c3[K144];
    __shared__ ull twiA[16*33];      // (c, s), cols 0..31
    __shared__ ull twiB[16*33];      // (-s, c)
    __shared__ float2 SA[256];       // xx = xl
    __shared__ float2 SB[256];       // xx = xl + 32
    int bj = blockIdx.x >> 4;        // b*16 + j
    int xo = blockIdx.x & 15;        // handles xl = 2*xo, 2*xo+1
    int b = bj >> 4, j = bj & 15;
    int t = threadIdx.x;             // 256
    if (t < K144) {
        float2 v = g_C3[(size_t)bj*K144 + t];
        c3[t] = pk(v.x, v.y);
    }
    for (int i = t; i < 512; i += 256) {
        int k = i >> 5, col = i & 31;
        int fk = k < 8 ? k : k - 16;
        float2 w = g_TW[(col * fk) & 63];
        twiA[k*33 + col] = pk(w.x, w.y);
        twiB[k*33 + col] = pk(-w.y, w.x);
    }
    __syncthreads();
    // inverse basis: xs2[kx] for t = ky*16+kz (coalesced YWT loads)
    ull xs2[16];
    #pragma unroll
    for (int kx = 0; kx < 16; kx++) {
        int m = (kx << 8) | t;
        int s = g_shell[m];
        ull acc = 0;
        #pragma unroll
        for (int l = 0; l < 9; l++)
            acc = ffma2(splat(g_YWT[l*M4096 + m]), c3[s*9 + l], acc);
        xs2[kx] = acc;
    }
    ull neg1 = splat(-1.f);
    int yp = t >> 3;
    int kzq = t & 7;
    #pragma unroll
    for (int xh = 0; xh < 2; xh++) {
        int xl = xo*2 + xh;
        // x-stage: out(xl) = E+O, out(xl+32) = E-O
        {
            ull E = 0, O = 0;
            #pragma unroll
            for (int kx = 0; kx < 16; kx++) {
                float2 v = upk(xs2[kx]);
                ull wA = twiA[kx*33 + xl], wB = twiB[kx*33 + xl];
                if (kx & 1) {
                    O = ffma2(splat(v.x), wA, O);
                    O = ffma2(splat(v.y), wB, O);
                } else {
                    E = ffma2(splat(v.x), wA, E);
                    E = ffma2(splat(v.y), wB, E);
                }
            }
            SA[t] = upk(add2(E, O));
            SB[t] = upk(ffma2(O, neg1, E));
        }
        __syncthreads();
        // y-stage
        #pragma unroll
        for (int xi = 0; xi < 2; xi++) {
            const float2* S = xi ? SB : SA;
            int xx = xl + 32*xi;
            float2 r0[2], r1[2];
            #pragma unroll
            for (int k2 = 0; k2 < 2; k2++) {
                int kz = kzq*2 + k2;
                ull E = 0, O = 0;
                #pragma unroll
                for (int ky = 0; ky < 16; ky++) {
                    float2 v = S[ky*16 + kz];
                    ull wA = twiA[ky*33 + yp], wB = twiB[ky*33 + yp];
                    if (ky & 1) {
                        O = ffma2(splat(v.x), wA, O);
                        O = ffma2(splat(v.y), wB, O);
                    } else {
                        E = ffma2(splat(v.x), wA, E);
                        E = ffma2(splat(v.y), wB, E);
                    }
                }
                r0[k2] = upk(add2(E, O));
                r1[k2] = upk(ffma2(O, neg1, E));
            }
            size_t base = ((size_t)b*64 + xx)*64;
            float4 w0 = make_float4(r0[0].x, r0[0].y, r0[1].x, r0[1].y);
            float4 w1 = make_float4(r1[0].x, r1[0].y, r1[1].x, r1[1].y);
            *(float4*)&g_T2[(base + yp)*256 + j*16 + kzq*2]      = w0;
            *(float4*)&g_T2[(base + yp + 32)*256 + j*16 + kzq*2] = w1;
        }
        __syncthreads();
    }
}

// ---------------- K8: fused epilogue (unchanged) ----------------
__device__ __forceinline__ float gelu_t(float v) {
    float u = 0.7978845608028654f * (v + 0.044715f * v * v * v);
    float e = __expf(2.0f * u);
    float th = 1.0f - 2.0f / (e + 1.0f);
    return 0.5f * v * (1.0f + th);
}

#define K8_SMEM 37376

__global__ void __launch_bounds__(128, 5)
k8_final(const float* __restrict__ x,
         const float* __restrict__ wgr,
         const float* __restrict__ w2r, const float* __restrict__ w2i,
         const float* __restrict__ b2r,
         float* __restrict__ out) {
    extern __shared__ char sm[];
    float* s_x   = (float*)sm;
    float* s_t2x = (float*)(sm + 16384);
    float* s_t2y = (float*)(sm + 18432);
    float* s_twc = (float*)(sm + 20480);
    float* s_tws = (float*)(sm + 24576);
    float* s_wcR = (float*)(sm + 28672);
    float* s_wcI = (float*)(sm + 30720);
    float* s_w2r = (float*)(sm + 32768);
    float* s_w2n = (float*)(sm + 34816);
    float* s_bcR = (float*)(sm + 36864);
    float* s_bcI = (float*)(sm + 36928);
    float* s_b2  = (float*)(sm + 36992);
    float* s_wg  = (float*)(sm + 37120);

    int blk = blockIdx.x;
    int b  = blk >> 11;
    int xc = (blk >> 5) & 63;
    int y0 = (blk & 31) * 2;
    int t = threadIdx.x;             // 128

    for (int i = t; i < 1024; i += 128) {
        int line = i >> 9, c = (i >> 4) & 31, zq = i & 15;
        float4 v = *(const float4*)&x[(((size_t)(b*32+c))*64 + xc)*4096 + (size_t)(y0+line)*64 + zq*4];
        *(float4*)&s_x[(line*32+c)*64 + zq*4] = v;
    }
    for (int i = t; i < 512; i += 128) {
        int line = i >> 8, q = i & 255;
        int j = q >> 4, kz = q & 15;
        float2 v = g_T2[((((size_t)b*64 + xc)*64) + (y0+line))*256 + q];
        s_t2x[(line*16 + kz)*16 + j] = v.x;
        s_t2y[(line*16 + kz)*16 + j] = v.y;
    }
    for (int i = t; i < 1024; i += 128) {
        int kz = i >> 6, z = i & 63;
        int fk = kz < 8 ? kz : kz - 16;
        float2 w = g_TW[(z*fk) & 63];
        s_twc[i] = w.x;
        s_tws[i] = w.y;
    }
    for (int i = t; i < 512; i += 128) {
        int c = i >> 4, j = i & 15;
        float2 wv = g_WC[j*32 + c];
        s_wcR[c*16 + j] = wv.x;
        s_wcI[c*16 + j] = wv.y;
        int jj = i >> 5, o = i & 31;
        s_w2r[jj*32 + o] = w2r[o*16 + jj];
        s_w2n[jj*32 + o] = -w2i[o*16 + jj];
    }
    if (t < 32) {
        s_b2[t] = b2r[t];
        s_wg[t] = wgr[t];
        if (t < 16) { float2 v = g_BC[t]; s_bcR[t] = v.x; s_bcI[t] = v.y; }
    }
    __syncthreads();

    int line = t >> 6, z = t & 63;
    const float* xl = &s_x[line*2048];

    ull accR[8], accI[8];
    #pragma unroll
    for (int jp = 0; jp < 8; jp++) {
        accR[jp] = *(const ull*)&s_bcR[jp*2];
        accI[jp] = *(const ull*)&s_bcI[jp*2];
    }
    #pragma unroll
    for (int kz = 0; kz < 16; kz++) {
        float cw = s_twc[kz*64 + z], sw = s_tws[kz*64 + z];
        ull sc = splat(cw), ss = splat(sw), sn = splat(-sw);
        const ulonglong2* tx = (const ulonglong2*)&s_t2x[(line*16 + kz)*16];
        const ulonglong2* ty = (const ulonglong2*)&s_t2y[(line*16 + kz)*16];
        #pragma unroll
        for (int p = 0; p < 4; p++) {
            ulonglong2 a = tx[p], bv = ty[p];
            accR[2*p]   = ffma2(a.x,  sc, accR[2*p]);
            accR[2*p]   = ffma2(bv.x, sn, accR[2*p]);
            accI[2*p]   = ffma2(a.x,  ss, accI[2*p]);
            accI[2*p]   = ffma2(bv.x, sc, accI[2*p]);
            accR[2*p+1] = ffma2(a.y,  sc, accR[2*p+1]);
            accR[2*p+1] = ffma2(bv.y, sn, accR[2*p+1]);
            accI[2*p+1] = ffma2(a.y,  ss, accI[2*p+1]);
            accI[2*p+1] = ffma2(bv.y, sc, accI[2*p+1]);
        }
    }
    #pragma unroll 4
    for (int c = 0; c < 32; c++) {
        ull sx = splat(xl[c*64 + z]);
        const ulonglong2* wr = (const ulonglong2*)&s_wcR[c*16];
        const ulonglong2* wi = (const ulonglong2*)&s_wcI[c*16];
        #pragma unroll
        for (int p = 0; p < 4; p++) {
            ulonglong2 a = wr[p], bv = wi[p];
            accR[2*p]   = ffma2(a.x,  sx, accR[2*p]);
            accR[2*p+1] = ffma2(a.y,  sx, accR[2*p+1]);
            accI[2*p]   = ffma2(bv.x, sx, accI[2*p]);
            accI[2*p+1] = ffma2(bv.y, sx, accI[2*p+1]);
        }
    }

    float hrf[16], hif[16];
    #pragma unroll
    for (int jp = 0; jp < 8; jp++) {
        float2 r  = upk(accR[jp]);
        float2 im = upk(accI[jp]);
        hrf[2*jp]   = gelu_t(r.x);
        hrf[2*jp+1] = gelu_t(r.y);
        hif[2*jp]   = gelu_t(im.x);
        hif[2*jp+1] = gelu_t(im.y);
    }

    int y = y0 + line;
    size_t obase = (((size_t)(b*32))*64 + xc)*4096 + (size_t)y*64 + z;
    #pragma unroll
    for (int h = 0; h < 2; h++) {
        ull accO[8];
        #pragma unroll
        for (int op = 0; op < 8; op++) {
            int o = h*16 + op*2;
            ull b2p = *(const ull*)&s_b2[o];
            ull wgp = *(const ull*)&s_wg[o];
            ull xp  = pk(xl[o*64 + z], xl[(o+1)*64 + z]);
            accO[op] = ffma2(xp, wgp, b2p);
        }
        #pragma unroll
        for (int j = 0; j < 16; j++) {
            ull shr = splat(hrf[j]), shi = splat(hif[j]);
            const ulonglong2* wr = (const ulonglong2*)&s_w2r[j*32 + h*16];
            const ulonglong2* wn = (const ulonglong2*)&s_w2n[j*32 + h*16];
            #pragma unroll
            for (int p = 0; p < 4; p++) {
                ulonglong2 a = wr[p], bv = wn[p];
                accO[2*p]   = ffma2(a.x,  shr, accO[2*p]);
                accO[2*p]   = ffma2(bv.x, shi, accO[2*p]);
                accO[2*p+1] = ffma2(a.y,  shr, accO[2*p+1]);
                accO[2*p+1] = ffma2(bv.y, shi, accO[2*p+1]);
            }
        }
        #pragma unroll
        for (int op = 0; op < 8; op++) {
            int o = h*16 + op*2;
            float2 v = upk(accO[op]);
            out[obase + (size_t)o     * 262144] = v.x;
            out[obase + (size_t)(o+1) * 262144] = v.y;
        }
    }
}

// ---------------- launch ----------------
extern "C" void kernel_launch(void* const* d_in, const int* in_sizes, int n_in,
                              void* d_out, int out_size) {
    const float* x    = (const float*)d_in[0];
    const float* wfr  = (const float*)d_in[1];
    const float* wfi  = (const float*)d_in[2];
    const float* bfr  = (const float*)d_in[3];
    const float* bfi  = (const float*)d_in[4];
    const float* wgr  = (const float*)d_in[5];
    const float* wsr  = (const float*)d_in[7];
    const float* wsi  = (const float*)d_in[8];
    const float* w1r  = (const float*)d_in[9];
    const float* w1i  = (const float*)d_in[10];
    const float* b1r  = (const float*)d_in[11];
    const float* b1i  = (const float*)d_in[12];
    const float* w2r  = (const float*)d_in[13];
    const float* w2i  = (const float*)d_in[14];
    const float* b2r  = (const float*)d_in[15];
    float* out = (float*)d_out;

    cudaFuncSetAttribute(k8_final, cudaFuncAttributeMaxDynamicSharedMemorySize, K8_SMEM);

    k0a_init<<<32, 128>>>();
    k0b_sort<<<16, 256>>>();
    kpre<<<1, 512>>>(wfr, wfi, bfr, bfi, w1r, w1i, b1r, b1i);
    k12_fwd<<<BB*CC*64, 256>>>(x);
    k3_xdft<<<BB*CC*4, 256>>>();
    k4_proj<<<BB*CC*4, 256>>>();
    k5_conv<<<BB*K144, 32>>>(wsr, wsi, w1r, w1i);
    k67_inv<<<BB*HID*16, 256>>>();
    k8_final<<<BB*64*32, 128, K8_SMEM>>>(x, wgr, w2r, w2i, b2r, out);
}